// round 3
// baseline (speedup 1.0000x reference)
#include <cuda_runtime.h>
#include <math.h>

#define BN_INV 0.9999950000374997f

// ---------------- scratch (device globals; no allocations allowed) -----------
__device__ float g_p1[8 * 32 * 128 * 128];   // maxpool(e1)
__device__ float g_p2[8 * 64 * 64 * 64];     // maxpool(e2)
__device__ float g_p3[8 * 128 * 32 * 32];    // maxpool(e3)
__device__ float g_e4[8 * 256 * 32 * 32];    // conv4 output
__device__ float g_A [256 * 16 * 16];        // per-channel quadratic forms

// ---------------- conv1: Cin=1 -> Cout=32, H=W=256, pad 1, BN+ReLU ----------
// grid (4,16,8), block 256 = 16x16. Each thread: 4 consecutive x pixels, all 32 oc.
__global__ __launch_bounds__(256) void conv1_kernel(
    const float* __restrict__ x, const float* __restrict__ w,
    const float* __restrict__ g, const float* __restrict__ b,
    float* __restrict__ out)
{
    __shared__ float ws[32 * 9];
    __shared__ float ss[32], bs[32];
    __shared__ float tile[18][66];

    const int tid = threadIdx.x;
    for (int i = tid; i < 288; i += 256) ws[i] = w[i];
    if (tid < 32) {
        ss[tid] = g[tid] * BN_INV;
        bs[tid] = b[tid];
    }
    const int n  = blockIdx.z;
    const int y0 = blockIdx.y * 16;
    const int x0 = blockIdx.x * 64;
    const float* xp = x + (long)n * 65536;

    for (int i = tid; i < 18 * 66; i += 256) {
        int r = i / 66, c = i % 66;
        int yy = y0 - 1 + r, xx = x0 - 1 + c;
        float v = 0.f;
        if (yy >= 0 && yy < 256 && xx >= 0 && xx < 256) v = xp[yy * 256 + xx];
        tile[r][c] = v;
    }
    __syncthreads();

    const int tx = tid & 15, ty = tid >> 4;
    float win[3][6];
#pragma unroll
    for (int r = 0; r < 3; r++)
#pragma unroll
        for (int c = 0; c < 6; c++) win[r][c] = tile[ty + r][tx * 4 + c];

    const int y = y0 + ty, xb = x0 + tx * 4;
    float* op = out + (long)n * 32 * 65536 + y * 256 + xb;

#pragma unroll
    for (int cb = 0; cb < 4; cb++) {
        float acc[8][4];
#pragma unroll
        for (int c = 0; c < 8; c++)
#pragma unroll
            for (int p = 0; p < 4; p++) acc[c][p] = 0.f;
#pragma unroll
        for (int c = 0; c < 8; c++) {
            int ch = cb * 8 + c;
#pragma unroll
            for (int ky = 0; ky < 3; ky++)
#pragma unroll
                for (int kx = 0; kx < 3; kx++) {
                    float wv = ws[ch * 9 + ky * 3 + kx];
#pragma unroll
                    for (int p = 0; p < 4; p++) acc[c][p] += wv * win[ky][kx + p];
                }
        }
#pragma unroll
        for (int c = 0; c < 8; c++) {
            int ch = cb * 8 + c;
            float s = ss[ch], bb = bs[ch];
            float4 v;
            v.x = fmaxf(acc[c][0] * s + bb, 0.f);
            v.y = fmaxf(acc[c][1] * s + bb, 0.f);
            v.z = fmaxf(acc[c][2] * s + bb, 0.f);
            v.w = fmaxf(acc[c][3] * s + bb, 0.f);
            *(float4*)(op + (long)ch * 65536) = v;
        }
    }
}

// ---------------- generic conv: Cin multiple of 16, BN+ReLU -----------------
// grid (W/32, H/8, N*Cout/32), block 256 = (tx:8, ty:8, tg:4)
// thread: 4 x-pixels x 8 oc register tile; cin chunked by 16 through smem.
#define CC 16
__global__ __launch_bounds__(256) void conv_kernel(
    const float* __restrict__ in, const float* __restrict__ w,
    const float* __restrict__ g, const float* __restrict__ b,
    float* __restrict__ out, int Cin, int H, int W, int Cout)
{
    __shared__ float in_s[CC][10][35];   // stride 35: conflict-free for 4*tx+3*ty
    __shared__ float w_s[CC * 9 * 32];   // [ic][kk][oc]
    __shared__ float ss[32], bs[32];

    const int tid = threadIdx.x;
    const int nOcb = Cout >> 5;
    const int n    = blockIdx.z / nOcb;
    const int ocb  = (blockIdx.z % nOcb) * 32;
    const int y0   = blockIdx.y * 8;
    const int x0   = blockIdx.x * 32;
    if (tid < 32) { ss[tid] = g[ocb + tid] * BN_INV; bs[tid] = b[ocb + tid]; }

    const int tx = tid & 7, ty = (tid >> 3) & 7, tg = tid >> 6;
    const long HW = (long)H * W;

    float acc[8][4];
#pragma unroll
    for (int o = 0; o < 8; o++)
#pragma unroll
        for (int p = 0; p < 4; p++) acc[o][p] = 0.f;

    for (int ic0 = 0; ic0 < Cin; ic0 += CC) {
        __syncthreads();
        // input tile: rows y0-1..y0+8, cols x0-1..x0+32 (10 x 34) x 16 ic
        for (int i = tid; i < CC * 10 * 34; i += 256) {
            int ic = i / 340, rem = i % 340;
            int r = rem / 34, c = rem % 34;
            int yy = y0 - 1 + r, xx = x0 - 1 + c;
            float v = 0.f;
            if (yy >= 0 && yy < H && xx >= 0 && xx < W)
                v = in[((long)n * Cin + ic0 + ic) * HW + (long)yy * W + xx];
            in_s[ic][r][c] = v;
        }
        // weights OIHW -> [ic][kk][oc]
        for (int i = tid; i < CC * 9 * 32; i += 256) {
            int oc = i & 31;
            int rem = i >> 5;            // ic*9 + kk
            int kk = rem % 9, ic = rem / 9;
            w_s[i] = w[((long)(ocb + oc) * Cin + ic0 + ic) * 9 + kk];
        }
        __syncthreads();

        for (int ic = 0; ic < CC; ic++) {
#pragma unroll
            for (int ky = 0; ky < 3; ky++) {
                float rr[6];
#pragma unroll
                for (int c = 0; c < 6; c++) rr[c] = in_s[ic][ty + ky][tx * 4 + c];
#pragma unroll
                for (int kx = 0; kx < 3; kx++) {
                    const float4* wp = (const float4*)&w_s[(ic * 9 + ky * 3 + kx) * 32 + tg * 8];
                    float4 wa = wp[0], wb = wp[1];
                    float w8[8] = {wa.x, wa.y, wa.z, wa.w, wb.x, wb.y, wb.z, wb.w};
#pragma unroll
                    for (int o = 0; o < 8; o++)
#pragma unroll
                        for (int p = 0; p < 4; p++)
                            acc[o][p] += w8[o] * rr[kx + p];
                }
            }
        }
    }

    const int y = y0 + ty;
    float* op = out + ((long)n * Cout + ocb + tg * 8) * HW + (long)y * W + x0 + tx * 4;
#pragma unroll
    for (int o = 0; o < 8; o++) {
        float s = ss[tg * 8 + o], bb = bs[tg * 8 + o];
        float4 v;
        v.x = fmaxf(acc[o][0] * s + bb, 0.f);
        v.y = fmaxf(acc[o][1] * s + bb, 0.f);
        v.z = fmaxf(acc[o][2] * s + bb, 0.f);
        v.w = fmaxf(acc[o][3] * s + bb, 0.f);
        *(float4*)(op + (long)o * HW) = v;
    }
}

// ---------------- 2x2 maxpool, float4 vectorized -----------------------------
__global__ void pool_kernel(const float* __restrict__ in, float* __restrict__ out,
                            int Wi, int Wo, int Ho, long total4)
{
    long t = (long)blockIdx.x * blockDim.x + threadIdx.x;
    if (t >= total4) return;
    int wq = Wo >> 2;
    int xq = (int)(t % wq);
    long r = t / wq;
    int yo = (int)(r % Ho);
    long pl = r / Ho;
    const float* p0 = in + pl * (long)Wi * 2 * Ho + (long)(2 * yo) * Wi + xq * 8;
    const float* p1 = p0 + Wi;
    float4 a0 = ((const float4*)p0)[0], a1 = ((const float4*)p0)[1];
    float4 b0 = ((const float4*)p1)[0], b1 = ((const float4*)p1)[1];
    float4 o;
    o.x = fmaxf(fmaxf(a0.x, a0.y), fmaxf(b0.x, b0.y));
    o.y = fmaxf(fmaxf(a0.z, a0.w), fmaxf(b0.z, b0.w));
    o.z = fmaxf(fmaxf(a1.x, a1.y), fmaxf(b1.x, b1.y));
    o.w = fmaxf(fmaxf(a1.z, a1.w), fmaxf(b1.z, b1.w));
    *(float4*)(out + pl * (long)Ho * Wo + (long)yo * Wo + xq * 4) = o;
}

// ---------------- build per-channel quadratic form A = Re(U^H diag(zbar) U) --
// one thread per (channel c, column k): computes A[c][j][k] for all j.
__global__ void build_A_kernel(const float* __restrict__ w0,
                               const float* __restrict__ w1,
                               float* __restrict__ A)
{
    int t = blockIdx.x * blockDim.x + threadIdx.x;
    if (t >= 256 * 16) return;
    int c = t >> 4, k = t & 15;

    float gr[4][2][2], gi[4][2][2];
    float a0 = w0[c * 2 + 0], a1 = w0[c * 2 + 1];
    float z0 = w1[c * 2 + 0], z1 = w1[c * 2 + 1];
    const float isq2 = 0.7071067811865476f;
#pragma unroll
    for (int w = 0; w < 4; w++) {
        float ay = (w & 1) ? a1 : a0;
        float az = (w & 1) ? z1 : z0;
        float cy = cosf(ay * 0.5f), sy = sinf(ay * 0.5f);
        float cz = cosf(az * 0.5f), sz = sinf(az * 0.5f);
        float m00 = (cy - sy) * isq2, m01 = (cy + sy) * isq2;
        float m10 = (sy + cy) * isq2, m11 = (sy - cy) * isq2;
        gr[w][0][0] = m00 * cz; gi[w][0][0] = -m00 * sz;
        gr[w][0][1] = m01 * cz; gi[w][0][1] = -m01 * sz;
        gr[w][1][0] = m10 * cz; gi[w][1][0] =  m10 * sz;
        gr[w][1][1] = m11 * cz; gi[w][1][1] =  m11 * sz;
    }
    // PTOT = p01 o p12 o p23 o p30 (applied to b in that order)
    int P[16];
#pragma unroll
    for (int bb = 0; bb < 16; bb++) {
        int v = bb;
        if (v & 1) v ^= 8;   // CNOT(3,0)
        if (v & 2) v ^= 1;   // CNOT(2,3)
        if (v & 4) v ^= 2;   // CNOT(1,2)
        if (v & 8) v ^= 4;   // CNOT(0,1)
        P[bb] = v;
    }

    float acc[16];
#pragma unroll
    for (int j = 0; j < 16; j++) acc[j] = 0.f;

    for (int i = 0; i < 16; i++) {
        int r = P[i];
        float zi = (4 - 2 * __popc(i)) * 0.25f;
        int r0 = (r >> 3) & 1, r1 = (r >> 2) & 1, r2 = (r >> 1) & 1, r3 = r & 1;

        float t2r[2], t2i[2];
        t2r[0] = gr[0][r0][0]; t2i[0] = gi[0][r0][0];
        t2r[1] = gr[0][r0][1]; t2i[1] = gi[0][r0][1];
        float t4r[4], t4i[4];
#pragma unroll
        for (int j0 = 0; j0 < 2; j0++)
#pragma unroll
            for (int j1 = 0; j1 < 2; j1++) {
                float br = gr[1][r1][j1], bi = gi[1][r1][j1];
                t4r[j0 * 2 + j1] = t2r[j0] * br - t2i[j0] * bi;
                t4i[j0 * 2 + j1] = t2r[j0] * bi + t2i[j0] * br;
            }
        float t8r[8], t8i[8];
#pragma unroll
        for (int j = 0; j < 4; j++)
#pragma unroll
            for (int j2 = 0; j2 < 2; j2++) {
                float br = gr[2][r2][j2], bi = gi[2][r2][j2];
                t8r[j * 2 + j2] = t4r[j] * br - t4i[j] * bi;
                t8i[j * 2 + j2] = t4r[j] * bi + t4i[j] * br;
            }
        float ur[16], ui[16];
#pragma unroll
        for (int j = 0; j < 8; j++)
#pragma unroll
            for (int j3 = 0; j3 < 2; j3++) {
                float br = gr[3][r3][j3], bi = gi[3][r3][j3];
                ur[j * 2 + j3] = t8r[j] * br - t8i[j] * bi;
                ui[j * 2 + j3] = t8r[j] * bi + t8i[j] * br;
            }
        float ukr = ur[k], uki = ui[k];
#pragma unroll
        for (int j = 0; j < 16; j++)
            acc[j] += zi * (ur[j] * ukr + ui[j] * uki);
    }
#pragma unroll
    for (int j = 0; j < 16; j++) A[c * 256 + j * 16 + k] = acc[j];
}

// ---------------- quantum stage + BN5 + ReLU (fused) -------------------------
// one block per (n,c) plane (32x32). thread: 4 consecutive x outputs.
__global__ __launch_bounds__(256) void quantum_kernel(
    const float* __restrict__ e4, const float* __restrict__ A,
    const float* __restrict__ g5, const float* __restrict__ b5,
    float* __restrict__ out)
{
    __shared__ float tile[35 * 37];  // stride 37: conflict-free
    __shared__ float As[256];

    const int bc = blockIdx.x;       // n*256 + c
    const int c  = bc & 255;
    const int tid = threadIdx.x;

    for (int i = tid; i < 35 * 37; i += 256) tile[i] = 0.f;
    __syncthreads();
    const float* ep = e4 + (long)bc * 1024;
    for (int i = tid; i < 1024; i += 256) {
        int r = i >> 5, cc = i & 31;
        tile[(r + 1) * 37 + (cc + 1)] = ep[i];
    }
    if (tid < 256) As[tid] = A[c * 256 + tid];
    __syncthreads();

    const int y = tid >> 3, x4 = (tid & 7) * 4;
    float win[4][7];
#pragma unroll
    for (int r = 0; r < 4; r++)
#pragma unroll
        for (int cc = 0; cc < 7; cc++) win[r][cc] = tile[(y + r) * 37 + x4 + cc];

    float s[4] = {0.f, 0.f, 0.f, 0.f};
#pragma unroll
    for (int o = 0; o < 4; o++)
#pragma unroll
        for (int t = 0; t < 16; t++) {
            float v = win[t >> 2][(t & 3) + o];
            s[o] += v * v;
        }

    float quad[4] = {0.f, 0.f, 0.f, 0.f};
#pragma unroll
    for (int j = 0; j < 16; j++) {
        float t0 = 0.f, t1 = 0.f, t2 = 0.f, t3 = 0.f;
        int jr = j >> 2, jc = j & 3;
#pragma unroll
        for (int k = 0; k < 16; k++) {
            float a = As[j * 16 + k];
            int kr = k >> 2, kc = k & 3;
            t0 += a * win[kr][kc + 0];
            t1 += a * win[kr][kc + 1];
            t2 += a * win[kr][kc + 2];
            t3 += a * win[kr][kc + 3];
        }
        quad[0] += t0 * win[jr][jc + 0];
        quad[1] += t1 * win[jr][jc + 1];
        quad[2] += t2 * win[jr][jc + 2];
        quad[3] += t3 * win[jr][jc + 3];
    }

    const float sc = g5[c] * BN_INV, bb = b5[c];
    float4 v;
    v.x = fmaxf((0.5f * quad[0] / fmaxf(s[0], 1e-24f) + 0.5f) * sc + bb, 0.f);
    v.y = fmaxf((0.5f * quad[1] / fmaxf(s[1], 1e-24f) + 0.5f) * sc + bb, 0.f);
    v.z = fmaxf((0.5f * quad[2] / fmaxf(s[2], 1e-24f) + 0.5f) * sc + bb, 0.f);
    v.w = fmaxf((0.5f * quad[3] / fmaxf(s[3], 1e-24f) + 0.5f) * sc + bb, 0.f);
    *(float4*)(out + (long)bc * 1024 + y * 32 + x4) = v;
}

// -----------------------------------------------------------------------------
extern "C" void kernel_launch(void* const* d_in, const int* in_sizes, int n_in,
                              void* d_out, int out_size)
{
    (void)in_sizes; (void)n_in; (void)out_size;
    const float* x   = (const float*)d_in[0];
    const float* w1  = (const float*)d_in[1];
    const float* g1  = (const float*)d_in[2];
    const float* b1  = (const float*)d_in[3];
    const float* w2  = (const float*)d_in[4];
    const float* g2  = (const float*)d_in[5];
    const float* b2  = (const float*)d_in[6];
    const float* w3  = (const float*)d_in[7];
    const float* g3  = (const float*)d_in[8];
    const float* b3  = (const float*)d_in[9];
    const float* w4  = (const float*)d_in[10];
    const float* g4  = (const float*)d_in[11];
    const float* b4  = (const float*)d_in[12];
    const float* qw0 = (const float*)d_in[13];
    const float* qw1 = (const float*)d_in[14];
    const float* g5  = (const float*)d_in[15];
    const float* b5  = (const float*)d_in[16];

    float* out = (float*)d_out;
    float* e1 = out;
    float* e2 = out + 16777216;   // 8*32*256*256
    float* e3 = out + 25165824;   // + 8*64*128*128
    float* o4 = out + 29360128;   // + 8*128*64*64

    float *p1, *p2, *p3, *e4, *Ab;
    cudaGetSymbolAddress((void**)&p1, g_p1);
    cudaGetSymbolAddress((void**)&p2, g_p2);
    cudaGetSymbolAddress((void**)&p3, g_p3);
    cudaGetSymbolAddress((void**)&e4, g_e4);
    cudaGetSymbolAddress((void**)&Ab, g_A);

    // conv1: (8,1,256,256) -> e1 (8,32,256,256)
    conv1_kernel<<<dim3(4, 16, 8), 256>>>(x, w1, g1, b1, e1);
    // pool1 -> p1 (8,32,128,128)
    pool_kernel<<<4096, 256>>>(e1, p1, 256, 128, 128, 1048576L);
    // conv2 -> e2 (8,64,128,128)
    conv_kernel<<<dim3(4, 16, 8 * 2), 256>>>(p1, w2, g2, b2, e2, 32, 128, 128, 64);
    // pool2 -> p2 (8,64,64,64)
    pool_kernel<<<2048, 256>>>(e2, p2, 128, 64, 64, 524288L);
    // conv3 -> e3 (8,128,64,64)
    conv_kernel<<<dim3(2, 8, 8 * 4), 256>>>(p2, w3, g3, b3, e3, 64, 64, 64, 128);
    // pool3 -> p3 (8,128,32,32)
    pool_kernel<<<1024, 256>>>(e3, p3, 64, 32, 32, 262144L);
    // conv4 -> e4 (8,256,32,32)
    conv_kernel<<<dim3(1, 4, 8 * 8), 256>>>(p3, w4, g4, b4, e4, 128, 32, 32, 256);
    // quantum quadratic forms
    build_A_kernel<<<16, 256>>>(qw0, qw1, Ab);
    // quantum stage + BN5 + ReLU -> o4 (8,256,32,32)
    quantum_kernel<<<2048, 256>>>(e4, Ab, g5, b5, o4);
}

// round 5
// speedup vs baseline: 1.5209x; 1.5209x over previous
#include <cuda_runtime.h>
#include <cuda_bf16.h>
#include <math.h>
#include <stdint.h>

#define BN_INV 0.9999950000374997f

// ---------------- scratch (device globals) -----------------------------------
__device__ __align__(16) uint32_t g_p1h[8*128*128*16], g_p1l[8*128*128*16];
__device__ __align__(16) uint32_t g_p2h[8*64*64*32],   g_p2l[8*64*64*32];
__device__ __align__(16) uint32_t g_p3h[8*32*32*64],   g_p3l[8*32*32*64];
__device__ __align__(16) uint16_t g_B2h[9*64*40],   g_B2l[9*64*40];
__device__ __align__(16) uint16_t g_B3h[18*64*72],  g_B3l[18*64*72];
__device__ __align__(16) uint16_t g_B4h[72*64*72],  g_B4l[72*64*72];
__device__ float g_e4[8*256*32*32];
__device__ float g_A [256*16*16];

// ---------------- helpers -----------------------------------------------------
__device__ __forceinline__ uint32_t smem_to_u32(const void* p) {
    uint32_t a;
    asm("{ .reg .u64 t; cvta.to.shared.u64 t, %1; cvt.u32.u64 %0, t; }" : "=r"(a) : "l"(p));
    return a;
}
#define LDSM4(r, a) \
    asm volatile("ldmatrix.sync.aligned.m8n8.x4.shared.b16 {%0,%1,%2,%3}, [%4];" \
        : "=r"((r)[0]), "=r"((r)[1]), "=r"((r)[2]), "=r"((r)[3]) : "r"(a))

__device__ __forceinline__ void mma16816(float* c, const uint32_t* a, uint32_t b0, uint32_t b1) {
    asm volatile(
        "mma.sync.aligned.m16n8k16.row.col.f32.bf16.bf16.f32 "
        "{%0,%1,%2,%3}, {%4,%5,%6,%7}, {%8,%9}, {%0,%1,%2,%3};"
        : "+f"(c[0]), "+f"(c[1]), "+f"(c[2]), "+f"(c[3])
        : "r"(a[0]), "r"(a[1]), "r"(a[2]), "r"(a[3]), "r"(b0), "r"(b1));
}

// split: hi = top-16 truncation of (a,b) packed; lo = rn(x - hi) packed bf16x2
__device__ __forceinline__ void split2(float a, float b, uint32_t& hi2, uint32_t& lo2) {
    uint32_t au = __float_as_uint(a), bu = __float_as_uint(b);
    hi2 = __byte_perm(au, bu, 0x7632);
    float la = a - __uint_as_float(au & 0xFFFF0000u);
    float lb = b - __uint_as_float(bu & 0xFFFF0000u);
    __nv_bfloat162 l2 = __floats2bfloat162_rn(la, lb);
    lo2 = *reinterpret_cast<uint32_t*>(&l2);
}

// ======================= conv1 (fp32 direct, memory-bound) ===================
__global__ __launch_bounds__(256) void conv1_kernel(
    const float* __restrict__ x, const float* __restrict__ w,
    const float* __restrict__ g, const float* __restrict__ b,
    float* __restrict__ out)
{
    __shared__ float ws[288], ss[32], bs[32];
    __shared__ float tile[18][66];
    const int tid = threadIdx.x;
    for (int i = tid; i < 288; i += 256) ws[i] = w[i];
    if (tid < 32) { ss[tid] = g[tid] * BN_INV; bs[tid] = b[tid]; }
    const int n = blockIdx.z, y0 = blockIdx.y * 16, x0 = blockIdx.x * 64;
    const float* xp = x + (long)n * 65536;
    for (int i = tid; i < 18 * 66; i += 256) {
        int r = i / 66, c = i % 66, yy = y0 - 1 + r, xx = x0 - 1 + c;
        tile[r][c] = (yy >= 0 && yy < 256 && xx >= 0 && xx < 256) ? xp[yy * 256 + xx] : 0.f;
    }
    __syncthreads();
    const int tx = tid & 15, ty = tid >> 4;
    float win[3][6];
#pragma unroll
    for (int r = 0; r < 3; r++)
#pragma unroll
        for (int c = 0; c < 6; c++) win[r][c] = tile[ty + r][tx * 4 + c];
    float* op = out + (long)n * 32 * 65536 + (y0 + ty) * 256 + x0 + tx * 4;
#pragma unroll
    for (int cb = 0; cb < 4; cb++) {
        float acc[8][4];
#pragma unroll
        for (int c = 0; c < 8; c++)
#pragma unroll
            for (int p = 0; p < 4; p++) acc[c][p] = 0.f;
#pragma unroll
        for (int c = 0; c < 8; c++) {
            int ch = cb * 8 + c;
#pragma unroll
            for (int ky = 0; ky < 3; ky++)
#pragma unroll
                for (int kx = 0; kx < 3; kx++) {
                    float wv = ws[ch * 9 + ky * 3 + kx];
#pragma unroll
                    for (int p = 0; p < 4; p++) acc[c][p] += wv * win[ky][kx + p];
                }
        }
#pragma unroll
        for (int c = 0; c < 8; c++) {
            int ch = cb * 8 + c;
            float s = ss[ch], bb = bs[ch];
            float4 v;
            v.x = fmaxf(acc[c][0]*s+bb, 0.f); v.y = fmaxf(acc[c][1]*s+bb, 0.f);
            v.z = fmaxf(acc[c][2]*s+bb, 0.f); v.w = fmaxf(acc[c][3]*s+bb, 0.f);
            *(float4*)(op + (long)ch * 65536) = v;
        }
    }
}

// ======== pool: NCHW fp32 -> NHWC bf16 hi/lo words (2 channels per word) ======
__global__ __launch_bounds__(256) void pool_split_kernel(
    const float* __restrict__ in, uint32_t* __restrict__ oh, uint32_t* __restrict__ ol,
    int C, int Ho, int Wo, int total)
{
    int t = blockIdx.x * 256 + threadIdx.x;
    if (t >= total) return;
    const int CW = C >> 1;
    int cw = t % CW; int r = t / CW;
    int x = r % Wo; r /= Wo;
    int y = r % Ho; int n = r / Ho;
    const int Wi = Wo * 2, Hi = Ho * 2;
    long base = (((long)n * C + 2 * cw) * Hi + 2 * y) * Wi + 2 * x;
    long pl = (long)Hi * Wi;
    float a = fmaxf(fmaxf(in[base], in[base + 1]), fmaxf(in[base + Wi], in[base + Wi + 1]));
    float b = fmaxf(fmaxf(in[base + pl], in[base + pl + 1]),
                    fmaxf(in[base + pl + Wi], in[base + pl + Wi + 1]));
    uint32_t hw, lw;
    split2(a, b, hw, lw);
    long o = (((long)n * Ho + y) * Wo + x) * CW + cw;
    oh[o] = hw; ol[o] = lw;
}

// ======== pack weights OIHW fp32 -> padded [blk][64 oc][K ic] bf16 hi/lo ======
// blk = (ocb*9+pos)*nkc+kc ; row stride = K+8 uint16 (K*2+16 bytes).
__global__ void pack_w_kernel(const float* __restrict__ w,
                              uint16_t* __restrict__ oh, uint16_t* __restrict__ ol,
                              int Cin, int K, int nkc, int total)
{
    const int rw2 = K + 8;
    for (int e = blockIdx.x * 256 + threadIdx.x; e < total; e += gridDim.x * 256) {
        int ic = e % K;
        int t = e / K;
        int r = t % 64;
        int blk = t / 64;
        int kc = blk % nkc, t2 = blk / nkc;
        int pos = t2 % 9, ocb = t2 / 9;
        int icg = kc * 64 + ic, ocg = ocb * 64 + r;
        float v = w[((long)ocg * Cin + icg) * 9 + pos];
        uint32_t u = __float_as_uint(v);
        float vl = v - __uint_as_float(u & 0xFFFF0000u);
        long idx = (long)blk * 64 * rw2 + r * rw2 + ic;
        oh[idx] = (uint16_t)(u >> 16);
        ol[idx] = __bfloat16_as_ushort(__float2bfloat16(vl));
    }
}

// ======== mma.sync implicit-GEMM conv: M=128 pixels x N=64 oc ================
// grid (Mtiles, ocbs, 8), block 256 (8 warps: 4 along M x 2 along N).
__global__ __launch_bounds__(256) void conv_mma_kernel(
    const uint4* __restrict__ inh, const uint4* __restrict__ inl,
    const uint4* __restrict__ Bh, const uint4* __restrict__ Bl,
    const float* __restrict__ g, const float* __restrict__ b,
    float* __restrict__ out,
    int H, int W, int Wsh, int K, int CW4, int nkc, int Cout, int S, int Bw)
{
    extern __shared__ char sm[];
    const int strideA = K * 2 + 16;
    const int tid = threadIdx.x;
    const int ocb = blockIdx.y, n = blockIdx.z;
    const int rpt = 128 >> Wsh;
    const int y0 = blockIdx.x * rpt;

    char* Ah  = sm;
    char* Al  = Ah + 128 * strideA;
    char* Bhs = Al + 128 * strideA;
    char* Bls = Bhs + 64 * strideA;
    float* ss = (float*)(Bls + 64 * strideA);
    float* bs = ss + 64;

    if (tid < 64) { ss[tid] = g[ocb * 64 + tid] * BN_INV; bs[tid] = b[ocb * 64 + tid]; }

    const uint32_t smB = smem_to_u32(sm);
    const uint32_t AhU = smB, AlU = AhU + 128 * strideA;
    const uint32_t BhU = AlU + 128 * strideA, BlU = BhU + 64 * strideA;

    const int lane = tid & 31, warp = tid >> 5;
    const int wm = warp & 3, wn = warp >> 2;
    const int mbase = wm * 32, nbase = wn * 32;

    // ldmatrix lane geometry
    const int arow = lane & 15, acol = (lane >> 4) * 16;
    const int brow = (lane & 7) + ((lane >> 4) << 3), bcol = ((lane >> 3) & 1) * 16;

    float acc[2][4][4];
#pragma unroll
    for (int i = 0; i < 2; i++)
#pragma unroll
        for (int j = 0; j < 4; j++)
#pragma unroll
            for (int k = 0; k < 4; k++) acc[i][j][k] = 0.f;

    // gather geometry: thread -> pixel p, half hf
    const int p = tid >> 1, hf = tid & 1;
    const int hc = K >> 4;                  // uint4 per half per array
    const int px0 = p & (W - 1), pyr = p >> Wsh;

    for (int s = 0; s < S; s++) {
        int pos, kc;
        if (nkc == 2) { pos = s >> 1; kc = s & 1; } else { pos = s; kc = 0; }
        const int ky = pos / 3, kx = pos % 3;

        __syncthreads();   // previous MMA reads done before overwrite
        // ---- A gather ----
        {
            const int py = y0 + pyr + ky - 1, px = px0 + kx - 1;
            const bool ok = ((unsigned)px < (unsigned)W) && ((unsigned)py < (unsigned)H);
            const long src = (((long)n * H + py) * W + px) * CW4 + kc * 8 + hf * hc;
            const uint4 z = make_uint4(0, 0, 0, 0);
            char* rowh = Ah + p * strideA + hf * hc * 16;
            char* rowl = Al + p * strideA + hf * hc * 16;
#pragma unroll 4
            for (int j = 0; j < hc; j++) {
                *(uint4*)(rowh + j * 16) = ok ? inh[src + j] : z;
                *(uint4*)(rowl + j * 16) = ok ? inl[src + j] : z;
            }
        }
        // ---- B copy (pre-padded blocks, layout == smem layout) ----
        {
            const long bb = (long)((ocb * 9 + pos) * nkc + kc) * Bw;
            for (int i = tid; i < Bw; i += 256) {
                ((uint4*)Bhs)[i] = Bh[bb + i];
                ((uint4*)Bls)[i] = Bl[bb + i];
            }
        }
        __syncthreads();
        // ---- MMA phase ----
        for (int k16 = 0; k16 < (K >> 4); k16++) {
            uint32_t ah[2][4], al[2][4], bh[2][4], bl[2][4];
#pragma unroll
            for (int mt = 0; mt < 2; mt++) {
                uint32_t aaddr = AhU + (mbase + mt * 16 + arow) * strideA + k16 * 32 + acol;
                LDSM4(ah[mt], aaddr);
                LDSM4(al[mt], aaddr + (uint32_t)(128 * strideA));
            }
#pragma unroll
            for (int g2 = 0; g2 < 2; g2++) {
                uint32_t baddr = BhU + (nbase + g2 * 16 + brow) * strideA + k16 * 32 + bcol;
                LDSM4(bh[g2], baddr);
                LDSM4(bl[g2], baddr + (uint32_t)(64 * strideA));
            }
#pragma unroll
            for (int mt = 0; mt < 2; mt++)
#pragma unroll
                for (int nt = 0; nt < 4; nt++) {
                    const int g2 = nt >> 1, pr = (nt & 1) * 2;
                    mma16816(acc[mt][nt], ah[mt], bh[g2][pr], bh[g2][pr + 1]);
                    mma16816(acc[mt][nt], ah[mt], bl[g2][pr], bl[g2][pr + 1]);
                    mma16816(acc[mt][nt], al[mt], bh[g2][pr], bh[g2][pr + 1]);
                }
        }
    }

    // ---- epilogue: BN + ReLU, NCHW stores ----
    const long HW = (long)H * W;
    const int r0 = lane >> 2, cpair = (lane & 3) * 2;
    const long obase = ((long)n * Cout + ocb * 64) * HW;
#pragma unroll
    for (int mt = 0; mt < 2; mt++) {
        const int m1 = mbase + mt * 16 + r0, m2 = m1 + 8;
        const long b1 = obase + (long)(y0 + (m1 >> Wsh)) * W + (m1 & (W - 1));
        const long b2 = obase + (long)(y0 + (m2 >> Wsh)) * W + (m2 & (W - 1));
#pragma unroll
        for (int nt = 0; nt < 4; nt++) {
            const int nc = nbase + nt * 8 + cpair;
            const float s0 = ss[nc], s1 = ss[nc + 1], q0 = bs[nc], q1 = bs[nc + 1];
            out[b1 + (long)nc * HW]       = fmaxf(acc[mt][nt][0] * s0 + q0, 0.f);
            out[b1 + (long)(nc + 1) * HW] = fmaxf(acc[mt][nt][1] * s1 + q1, 0.f);
            out[b2 + (long)nc * HW]       = fmaxf(acc[mt][nt][2] * s0 + q0, 0.f);
            out[b2 + (long)(nc + 1) * HW] = fmaxf(acc[mt][nt][3] * s1 + q1, 0.f);
        }
    }
}

// ---------------- build per-channel quadratic form A = Re(U^H diag(zbar) U) --
__global__ void build_A_kernel(const float* __restrict__ w0,
                               const float* __restrict__ w1,
                               float* __restrict__ A)
{
    int t = blockIdx.x * blockDim.x + threadIdx.x;
    if (t >= 256 * 16) return;
    int c = t >> 4, k = t & 15;
    float gr[4][2][2], gi[4][2][2];
    float a0 = w0[c*2+0], a1 = w0[c*2+1], z0 = w1[c*2+0], z1 = w1[c*2+1];
    const float isq2 = 0.7071067811865476f;
#pragma unroll
    for (int w = 0; w < 4; w++) {
        float ay = (w & 1) ? a1 : a0, az = (w & 1) ? z1 : z0;
        float cy = cosf(ay*0.5f), sy = sinf(ay*0.5f);
        float cz = cosf(az*0.5f), sz = sinf(az*0.5f);
        float m00 = (cy-sy)*isq2, m01 = (cy+sy)*isq2;
        float m10 = (sy+cy)*isq2, m11 = (sy-cy)*isq2;
        gr[w][0][0]=m00*cz; gi[w][0][0]=-m00*sz;
        gr[w][0][1]=m01*cz; gi[w][0][1]=-m01*sz;
        gr[w][1][0]=m10*cz; gi[w][1][0]= m10*sz;
        gr[w][1][1]=m11*cz; gi[w][1][1]= m11*sz;
    }
    int P[16];
#pragma unroll
    for (int bb = 0; bb < 16; bb++) {
        int v = bb;
        if (v & 1) v ^= 8;
        if (v & 2) v ^= 1;
        if (v & 4) v ^= 2;
        if (v & 8) v ^= 4;
        P[bb] = v;
    }
    float acc[16];
#pragma unroll
    for (int j = 0; j < 16; j++) acc[j] = 0.f;
    for (int i = 0; i < 16; i++) {
        int r = P[i];
        float zi = (4 - 2 * __popc(i)) * 0.25f;
        int r0=(r>>3)&1, r1=(r>>2)&1, r2=(r>>1)&1, r3=r&1;
        float t2r[2], t2i[2];
        t2r[0]=gr[0][r0][0]; t2i[0]=gi[0][r0][0];
        t2r[1]=gr[0][r0][1]; t2i[1]=gi[0][r0][1];
        float t4r[4], t4i[4];
#pragma unroll
        for (int j0 = 0; j0 < 2; j0++)
#pragma unroll
            for (int j1 = 0; j1 < 2; j1++) {
                float br=gr[1][r1][j1], bi=gi[1][r1][j1];
                t4r[j0*2+j1]=t2r[j0]*br-t2i[j0]*bi;
                t4i[j0*2+j1]=t2r[j0]*bi+t2i[j0]*br;
            }
        float t8r[8], t8i[8];
#pragma unroll
        for (int j = 0; j < 4; j++)
#pragma unroll
            for (int j2 = 0; j2 < 2; j2++) {
                float br=gr[2][r2][j2], bi=gi[2][r2][j2];
                t8r[j*2+j2]=t4r[j]*br-t4i[j]*bi;
                t8i[j*2+j2]=t4r[j]*bi+t4i[j]*br;
            }
        float ur[16], ui[16];
#pragma unroll
        for (int j = 0; j < 8; j++)
#pragma unroll
            for (int j3 = 0; j3 < 2; j3++) {
                float br=gr[3][r3][j3], bi=gi[3][r3][j3];
                ur[j*2+j3]=t8r[j]*br-t8i[j]*bi;
                ui[j*2+j3]=t8r[j]*bi+t8i[j]*br;
            }
        float ukr = ur[k], uki = ui[k];
#pragma unroll
        for (int j = 0; j < 16; j++)
            acc[j] += zi * (ur[j]*ukr + ui[j]*uki);
    }
#pragma unroll
    for (int j = 0; j < 16; j++) A[c*256 + j*16 + k] = acc[j];
}

// ---------------- quantum stage + BN5 + ReLU (fused) -------------------------
__global__ __launch_bounds__(256) void quantum_kernel(
    const float* __restrict__ e4, const float* __restrict__ A,
    const float* __restrict__ g5, const float* __restrict__ b5,
    float* __restrict__ out)
{
    __shared__ float tile[35 * 37];
    __shared__ float As[256];
    const int bc = blockIdx.x, c = bc & 255, tid = threadIdx.x;
    for (int i = tid; i < 35 * 37; i += 256) tile[i] = 0.f;
    __syncthreads();
    const float* ep = e4 + (long)bc * 1024;
    for (int i = tid; i < 1024; i += 256) {
        int r = i >> 5, cc = i & 31;
        tile[(r + 1) * 37 + (cc + 1)] = ep[i];
    }
    if (tid < 256) As[tid] = A[c * 256 + tid];
    __syncthreads();
    const int y = tid >> 3, x4 = (tid & 7) * 4;
    float win[4][7];
#pragma unroll
    for (int r = 0; r < 4; r++)
#pragma unroll
        for (int cc = 0; cc < 7; cc++) win[r][cc] = tile[(y + r) * 37 + x4 + cc];
    float s[4] = {0.f, 0.f, 0.f, 0.f};
#pragma unroll
    for (int o = 0; o < 4; o++)
#pragma unroll
        for (int t = 0; t < 16; t++) {
            float v = win[t >> 2][(t & 3) + o];
            s[o] += v * v;
        }
    float quad[4] = {0.f, 0.f, 0.f, 0.f};
#pragma unroll
    for (int j = 0; j < 16; j++) {
        float t0 = 0.f, t1 = 0.f, t2 = 0.f, t3 = 0.f;
        int jr = j >> 2, jc = j & 3;
#pragma unroll
        for (int k = 0; k < 16; k++) {
            float a = As[j * 16 + k];
            int kr = k >> 2, kc = k & 3;
            t0 += a * win[kr][kc + 0];
            t1 += a * win[kr][kc + 1];
            t2 += a * win[kr][kc + 2];
            t3 += a * win[kr][kc + 3];
        }
        quad[0] += t0 * win[jr][jc + 0];
        quad[1] += t1 * win[jr][jc + 1];
        quad[2] += t2 * win[jr][jc + 2];
        quad[3] += t3 * win[jr][jc + 3];
    }
    const float sc = g5[c] * BN_INV, bb = b5[c];
    float4 v;
    v.x = fmaxf((0.5f*quad[0]/fmaxf(s[0],1e-24f)+0.5f)*sc+bb, 0.f);
    v.y = fmaxf((0.5f*quad[1]/fmaxf(s[1],1e-24f)+0.5f)*sc+bb, 0.f);
    v.z = fmaxf((0.5f*quad[2]/fmaxf(s[2],1e-24f)+0.5f)*sc+bb, 0.f);
    v.w = fmaxf((0.5f*quad[3]/fmaxf(s[3],1e-24f)+0.5f)*sc+bb, 0.f);
    *(float4*)(out + (long)bc * 1024 + y * 32 + x4) = v;
}

// -----------------------------------------------------------------------------
// dyn smem: K=32 -> 31232 B ; K=64 -> 55808 B
extern "C" void kernel_launch(void* const* d_in, const int* in_sizes, int n_in,
                              void* d_out, int out_size)
{
    (void)in_sizes; (void)n_in; (void)out_size;
    const float* x   = (const float*)d_in[0];
    const float* w1  = (const float*)d_in[1];
    const float* g1  = (const float*)d_in[2];
    const float* b1  = (const float*)d_in[3];
    const float* w2  = (const float*)d_in[4];
    const float* g2  = (const float*)d_in[5];
    const float* b2  = (const float*)d_in[6];
    const float* w3  = (const float*)d_in[7];
    const float* g3  = (const float*)d_in[8];
    const float* b3  = (const float*)d_in[9];
    const float* w4  = (const float*)d_in[10];
    const float* g4  = (const float*)d_in[11];
    const float* b4  = (const float*)d_in[12];
    const float* qw0 = (const float*)d_in[13];
    const float* qw1 = (const float*)d_in[14];
    const float* g5  = (const float*)d_in[15];
    const float* b5  = (const float*)d_in[16];

    float* out = (float*)d_out;
    float* e1 = out;
    float* e2 = out + 16777216;
    float* e3 = out + 25165824;
    float* o4 = out + 29360128;

    uint32_t *p1h, *p1l, *p2h, *p2l, *p3h, *p3l;
    uint16_t *B2h, *B2l, *B3h, *B3l, *B4h, *B4l;
    float *e4, *Ab;
    cudaGetSymbolAddress((void**)&p1h, g_p1h); cudaGetSymbolAddress((void**)&p1l, g_p1l);
    cudaGetSymbolAddress((void**)&p2h, g_p2h); cudaGetSymbolAddress((void**)&p2l, g_p2l);
    cudaGetSymbolAddress((void**)&p3h, g_p3h); cudaGetSymbolAddress((void**)&p3l, g_p3l);
    cudaGetSymbolAddress((void**)&B2h, g_B2h); cudaGetSymbolAddress((void**)&B2l, g_B2l);
    cudaGetSymbolAddress((void**)&B3h, g_B3h); cudaGetSymbolAddress((void**)&B3l, g_B3l);
    cudaGetSymbolAddress((void**)&B4h, g_B4h); cudaGetSymbolAddress((void**)&B4l, g_B4l);
    cudaGetSymbolAddress((void**)&e4, g_e4);   cudaGetSymbolAddress((void**)&Ab, g_A);

    cudaFuncSetAttribute(conv_mma_kernel, cudaFuncAttributeMaxDynamicSharedMemorySize, 55808);

    // conv1 -> e1 (fp32 exact)
    conv1_kernel<<<dim3(4, 16, 8), 256>>>(x, w1, g1, b1, e1);
    // weight packing (independent)
    pack_w_kernel<<<72, 256>>>(w2, B2h, B2l, 32, 32, 1, 18432);
    pack_w_kernel<<<288, 256>>>(w3, B3h, B3l, 64, 64, 1, 73728);
    pack_w_kernel<<<1152, 256>>>(w4, B4h, B4l, 128, 64, 2, 294912);
    // pool1: e1 (8,32,256,256) -> p1 NHWC 32ch bf16 hi/lo (128x128)
    pool_split_kernel<<<8192, 256>>>(e1, p1h, p1l, 32, 128, 128, 2097152);
    // conv2 -> e2 (8,64,128,128)
    conv_mma_kernel<<<dim3(128, 1, 8), 256, 31232>>>(
        (const uint4*)p1h, (const uint4*)p1l, (const uint4*)B2h, (const uint4*)B2l,
        g2, b2, e2, 128, 128, 7, 32, 4, 1, 64, 9, 320);
    // pool2: e2 -> p2 NHWC 64ch (64x64)
    pool_split_kernel<<<4096, 256>>>(e2, p2h, p2l, 64, 64, 64, 1048576);
    // conv3 -> e3 (8,128,64,64)
    conv_mma_kernel<<<dim3(32, 2, 8), 256, 55808>>>(
        (const uint4*)p2h, (const uint4*)p2l, (const uint4*)B3h, (const uint4*)B3l,
        g3, b3, e3, 64, 64, 6, 64, 8, 1, 128, 9, 576);
    // pool3: e3 -> p3 NHWC 128ch (32x32)
    pool_split_kernel<<<2048, 256>>>(e3, p3h, p3l, 128, 32, 32, 524288);
    // conv4 -> e4 (8,256,32,32)
    conv_mma_kernel<<<dim3(8, 4, 8), 256, 55808>>>(
        (const uint4*)p3h, (const uint4*)p3l, (const uint4*)B4h, (const uint4*)B4l,
        g4, b4, e4, 32, 32, 5, 64, 16, 2, 256, 18, 576);
    // quantum
    build_A_kernel<<<16, 256>>>(qw0, qw1, Ab);
    quantum_kernel<<<2048, 256>>>(e4, Ab, g5, b5, o4);
}

// round 6
// speedup vs baseline: 1.8134x; 1.1923x over previous
#include <cuda_runtime.h>
#include <cuda_bf16.h>
#include <math.h>
#include <stdint.h>

#define BN_INV 0.9999950000374997f

// ---------------- scratch (device globals) -----------------------------------
__device__ __align__(16) uint32_t g_p1h[8*128*128*16], g_p1l[8*128*128*16];
__device__ __align__(16) uint32_t g_p2h[8*64*64*32],   g_p2l[8*64*64*32];
__device__ __align__(16) uint32_t g_p3h[8*32*32*64],   g_p3l[8*32*32*64];
__device__ __align__(16) uint16_t g_B2h[9*64*40],   g_B2l[9*64*40];
__device__ __align__(16) uint16_t g_B3h[18*64*72],  g_B3l[18*64*72];
__device__ __align__(16) uint16_t g_B4h[72*64*72],  g_B4l[72*64*72];
__device__ float g_e4[8*256*32*32];
__device__ float g_A [256*16*16];

// ---------------- helpers -----------------------------------------------------
__device__ __forceinline__ uint32_t smem_to_u32(const void* p) {
    uint32_t a;
    asm("{ .reg .u64 t; cvta.to.shared.u64 t, %1; cvt.u32.u64 %0, t; }" : "=r"(a) : "l"(p));
    return a;
}
#define LDSM4(r, a) \
    asm volatile("ldmatrix.sync.aligned.m8n8.x4.shared.b16 {%0,%1,%2,%3}, [%4];" \
        : "=r"((r)[0]), "=r"((r)[1]), "=r"((r)[2]), "=r"((r)[3]) : "r"(a))

__device__ __forceinline__ void mma16816(float* c, const uint32_t* a, uint32_t b0, uint32_t b1) {
    asm volatile(
        "mma.sync.aligned.m16n8k16.row.col.f32.bf16.bf16.f32 "
        "{%0,%1,%2,%3}, {%4,%5,%6,%7}, {%8,%9}, {%0,%1,%2,%3};"
        : "+f"(c[0]), "+f"(c[1]), "+f"(c[2]), "+f"(c[3])
        : "r"(a[0]), "r"(a[1]), "r"(a[2]), "r"(a[3]), "r"(b0), "r"(b1));
}

// split: hi = top-16 truncation of (a,b) packed; lo = rn(x - hi) packed bf16x2
__device__ __forceinline__ void split2(float a, float b, uint32_t& hi2, uint32_t& lo2) {
    uint32_t au = __float_as_uint(a), bu = __float_as_uint(b);
    hi2 = __byte_perm(au, bu, 0x7632);
    float la = a - __uint_as_float(au & 0xFFFF0000u);
    float lb = b - __uint_as_float(bu & 0xFFFF0000u);
    __nv_bfloat162 l2 = __floats2bfloat162_rn(la, lb);
    lo2 = *reinterpret_cast<uint32_t*>(&l2);
}

// ======================= conv1 (fp32 direct, memory-bound) ===================
__global__ __launch_bounds__(256) void conv1_kernel(
    const float* __restrict__ x, const float* __restrict__ w,
    const float* __restrict__ g, const float* __restrict__ b,
    float* __restrict__ out)
{
    __shared__ float ws[288], ss[32], bs[32];
    __shared__ float tile[18][66];
    const int tid = threadIdx.x;
    for (int i = tid; i < 288; i += 256) ws[i] = w[i];
    if (tid < 32) { ss[tid] = g[tid] * BN_INV; bs[tid] = b[tid]; }
    const int n = blockIdx.z, y0 = blockIdx.y * 16, x0 = blockIdx.x * 64;
    const float* xp = x + (long)n * 65536;
    for (int i = tid; i < 18 * 66; i += 256) {
        int r = i / 66, c = i % 66, yy = y0 - 1 + r, xx = x0 - 1 + c;
        tile[r][c] = (yy >= 0 && yy < 256 && xx >= 0 && xx < 256) ? xp[yy * 256 + xx] : 0.f;
    }
    __syncthreads();
    const int tx = tid & 15, ty = tid >> 4;
    float win[3][6];
#pragma unroll
    for (int r = 0; r < 3; r++)
#pragma unroll
        for (int c = 0; c < 6; c++) win[r][c] = tile[ty + r][tx * 4 + c];
    float* op = out + (long)n * 32 * 65536 + (y0 + ty) * 256 + x0 + tx * 4;
#pragma unroll
    for (int cb = 0; cb < 4; cb++) {
        float acc[8][4];
#pragma unroll
        for (int c = 0; c < 8; c++)
#pragma unroll
            for (int p = 0; p < 4; p++) acc[c][p] = 0.f;
#pragma unroll
        for (int c = 0; c < 8; c++) {
            int ch = cb * 8 + c;
#pragma unroll
            for (int ky = 0; ky < 3; ky++)
#pragma unroll
                for (int kx = 0; kx < 3; kx++) {
                    float wv = ws[ch * 9 + ky * 3 + kx];
#pragma unroll
                    for (int p = 0; p < 4; p++) acc[c][p] += wv * win[ky][kx + p];
                }
        }
#pragma unroll
        for (int c = 0; c < 8; c++) {
            int ch = cb * 8 + c;
            float s = ss[ch], bb = bs[ch];
            float4 v;
            v.x = fmaxf(acc[c][0]*s+bb, 0.f); v.y = fmaxf(acc[c][1]*s+bb, 0.f);
            v.z = fmaxf(acc[c][2]*s+bb, 0.f); v.w = fmaxf(acc[c][3]*s+bb, 0.f);
            *(float4*)(op + (long)ch * 65536) = v;
        }
    }
}

// ======== pool: NCHW fp32 -> NHWC bf16 hi/lo words (2 channels per word) ======
__global__ __launch_bounds__(256) void pool_split_kernel(
    const float* __restrict__ in, uint32_t* __restrict__ oh, uint32_t* __restrict__ ol,
    int C, int Ho, int Wo, int total)
{
    int t = blockIdx.x * 256 + threadIdx.x;
    if (t >= total) return;
    const int CW = C >> 1;
    int cw = t % CW; int r = t / CW;
    int x = r % Wo; r /= Wo;
    int y = r % Ho; int n = r / Ho;
    const int Wi = Wo * 2, Hi = Ho * 2;
    long base = (((long)n * C + 2 * cw) * Hi + 2 * y) * Wi + 2 * x;
    long pl = (long)Hi * Wi;
    float a = fmaxf(fmaxf(in[base], in[base + 1]), fmaxf(in[base + Wi], in[base + Wi + 1]));
    float b = fmaxf(fmaxf(in[base + pl], in[base + pl + 1]),
                    fmaxf(in[base + pl + Wi], in[base + pl + Wi + 1]));
    uint32_t hw, lw;
    split2(a, b, hw, lw);
    long o = (((long)n * Ho + y) * Wo + x) * CW + cw;
    oh[o] = hw; ol[o] = lw;
}

// ======== pack weights OIHW fp32 -> padded [blk][64 oc][K ic] bf16 hi/lo ======
// blk = (ocb*9+pos)*nkc+kc ; row stride = K+8 uint16 (K*2+16 bytes).
__global__ void pack_w_kernel(const float* __restrict__ w,
                              uint16_t* __restrict__ oh, uint16_t* __restrict__ ol,
                              int Cin, int K, int nkc, int total)
{
    const int rw2 = K + 8;
    for (int e = blockIdx.x * 256 + threadIdx.x; e < total; e += gridDim.x * 256) {
        int ic = e % K;
        int t = e / K;
        int r = t % 64;
        int blk = t / 64;
        int kc = blk % nkc, t2 = blk / nkc;
        int pos = t2 % 9, ocb = t2 / 9;
        int icg = kc * 64 + ic, ocg = ocb * 64 + r;
        float v = w[((long)ocg * Cin + icg) * 9 + pos];
        uint32_t u = __float_as_uint(v);
        float vl = v - __uint_as_float(u & 0xFFFF0000u);
        long idx = (long)blk * 64 * rw2 + r * rw2 + ic;
        oh[idx] = (uint16_t)(u >> 16);
        ol[idx] = __bfloat16_as_ushort(__float2bfloat16(vl));
    }
}

// ======== mma.sync implicit-GEMM conv v2 ======================================
// M=128 pixels x N=64 oc per CTA; per (ky,kc): gather A once (rpt segments of
// W+2 rows), load 3 kx B blocks, run 3x(K/16) MMA phases; smem-staged epilogue.
__global__ __launch_bounds__(256) void conv_mma_kernel(
    const uint4* __restrict__ inh, const uint4* __restrict__ inl,
    const uint4* __restrict__ Bh, const uint4* __restrict__ Bl,
    const float* __restrict__ g, const float* __restrict__ b,
    float* __restrict__ out,
    int H, int W, int Wsh, int rpt, int K, int CW4, int nkc, int Cout)
{
    extern __shared__ char sm[];
    const int strideA = K * 2 + 16;
    const int Wp2 = W + 2;
    const int rowsA = rpt * Wp2;
    const int hsh = (K == 32) ? 2 : 3;       // uint4 per row per array = K/8
    const int hc4m = (K >> 3) - 1;
    const int Bw4 = 4 * strideA;             // uint4 per tap per array (64*strideA/16)
    const int tid = threadIdx.x;
    const int ocb = blockIdx.y, n = blockIdx.z;
    const int y0 = blockIdx.x * rpt;

    char* Ah  = sm;
    char* Al  = Ah + rowsA * strideA;
    char* Bhs = Al + rowsA * strideA;
    char* Bls = Bhs + 3 * 64 * strideA;
    float* ss = (float*)(Bls + 3 * 64 * strideA);
    float* bs = ss + 64;
    float* stage = (float*)sm;               // reused after final sync

    if (tid < 64) { ss[tid] = g[ocb * 64 + tid] * BN_INV; bs[tid] = b[ocb * 64 + tid]; }

    const uint32_t AhU = smem_to_u32(sm);
    const uint32_t AlU = AhU + rowsA * strideA;
    const uint32_t BhU = AlU + rowsA * strideA;
    const uint32_t BlU = BhU + 3 * 64 * strideA;

    const int lane = tid & 31, warp = tid >> 5;
    const int wm = warp & 3, wn = warp >> 2;
    const int mbase = wm * 32, nbase = wn * 32;

    // ldmatrix lane geometry
    const int arow = lane & 15, acol = (lane >> 4) * 16;
    const int brow = (lane & 7) + ((lane >> 4) << 3), bcol = ((lane >> 3) & 1) * 16;

    // per-thread A row base for each mt (kx=0): seg*(W+2) + px
    int aRowBase[2];
#pragma unroll
    for (int mt = 0; mt < 2; mt++) {
        int m = mbase + mt * 16 + arow;
        aRowBase[mt] = (m >> Wsh) * Wp2 + (m & (W - 1));
    }

    float acc[2][4][4];
#pragma unroll
    for (int i = 0; i < 2; i++)
#pragma unroll
        for (int j = 0; j < 4; j++)
#pragma unroll
            for (int k = 0; k < 4; k++) acc[i][j][k] = 0.f;

    const int totA = rowsA << hsh;
    const uint4 z = make_uint4(0, 0, 0, 0);

    for (int ky = 0; ky < 3; ky++) {
        for (int kc = 0; kc < nkc; kc++) {
            __syncthreads();   // prior MMA reads done before overwrite
            // ---- A gather: rpt segments of (W+2) rows, tap-shared ----
            for (int i = tid; i < totA; i += 256) {
                int row = i >> hsh, j = i & hc4m;
                int seg = row / Wp2;
                int px = row - seg * Wp2 - 1;
                int py = y0 + seg + ky - 1;
                bool ok = ((unsigned)px < (unsigned)W) && ((unsigned)py < (unsigned)H);
                long src = (((long)n * H + py) * W + px) * CW4 + kc * 8 + j;
                *(uint4*)(Ah + row * strideA + j * 16) = ok ? inh[src] : z;
                *(uint4*)(Al + row * strideA + j * 16) = ok ? inl[src] : z;
            }
            // ---- B: 3 kx taps for this (ky,kc) ----
            {
                const int blk0 = (ocb * 9 + ky * 3) * nkc + kc;
                for (int i = tid; i < 3 * Bw4; i += 256) {
                    int tap = i / Bw4, r = i - tap * Bw4;
                    long gsrc = (long)(blk0 + tap * nkc) * Bw4 + r;
                    ((uint4*)Bhs)[i] = Bh[gsrc];
                    ((uint4*)Bls)[i] = Bl[gsrc];
                }
            }
            __syncthreads();
            // ---- MMA: 3 kx taps x K/16 ----
            for (int kx = 0; kx < 3; kx++) {
                for (int k16 = 0; k16 < (K >> 4); k16++) {
                    uint32_t ah[2][4], al[2][4], bh[2][4], bl[2][4];
#pragma unroll
                    for (int mt = 0; mt < 2; mt++) {
                        uint32_t aaddr = AhU + (uint32_t)(aRowBase[mt] + kx) * strideA
                                       + k16 * 32 + acol;
                        LDSM4(ah[mt], aaddr);
                        LDSM4(al[mt], aaddr + (uint32_t)(rowsA * strideA));
                    }
#pragma unroll
                    for (int g2 = 0; g2 < 2; g2++) {
                        uint32_t baddr = BhU + (uint32_t)(kx * 64 + nbase + g2 * 16 + brow) * strideA
                                       + k16 * 32 + bcol;
                        LDSM4(bh[g2], baddr);
                        LDSM4(bl[g2], baddr + (uint32_t)(3 * 64 * strideA));
                    }
#pragma unroll
                    for (int mt = 0; mt < 2; mt++)
#pragma unroll
                        for (int nt = 0; nt < 4; nt++) {
                            const int g2 = nt >> 1, pr = (nt & 1) * 2;
                            mma16816(acc[mt][nt], ah[mt], bh[g2][pr], bh[g2][pr + 1]);
                            mma16816(acc[mt][nt], ah[mt], bl[g2][pr], bl[g2][pr + 1]);
                            mma16816(acc[mt][nt], al[mt], bh[g2][pr], bh[g2][pr + 1]);
                        }
                }
            }
        }
    }

    // ---- epilogue: stage in smem ([oc][pixel], stride 132), coalesced stores --
    __syncthreads();
    {
        const int r0 = lane >> 2, cpair = (lane & 3) * 2;
#pragma unroll
        for (int mt = 0; mt < 2; mt++) {
            const int m1 = mbase + mt * 16 + r0, m2 = m1 + 8;
#pragma unroll
            for (int nt = 0; nt < 4; nt++) {
                const int nc = nbase + nt * 8 + cpair;
                stage[nc * 132 + m1]       = acc[mt][nt][0];
                stage[(nc + 1) * 132 + m1] = acc[mt][nt][1];
                stage[nc * 132 + m2]       = acc[mt][nt][2];
                stage[(nc + 1) * 132 + m2] = acc[mt][nt][3];
            }
        }
    }
    __syncthreads();
    {
        const long HW = (long)H * W;
        const long obase = ((long)n * Cout + ocb * 64) * HW;
        for (int i = tid; i < 8192; i += 256) {
            int oc = i >> 7, p = i & 127;
            int y = y0 + (p >> Wsh), x = p & (W - 1);
            float v = fmaxf(stage[oc * 132 + p] * ss[oc] + bs[oc], 0.f);
            out[obase + (long)oc * HW + (long)y * W + x] = v;
        }
    }
}

// ---------------- build per-channel quadratic form A = Re(U^H diag(zbar) U) --
__global__ void build_A_kernel(const float* __restrict__ w0,
                               const float* __restrict__ w1,
                               float* __restrict__ A)
{
    int t = blockIdx.x * blockDim.x + threadIdx.x;
    if (t >= 256 * 16) return;
    int c = t >> 4, k = t & 15;
    float gr[4][2][2], gi[4][2][2];
    float a0 = w0[c*2+0], a1 = w0[c*2+1], z0 = w1[c*2+0], z1 = w1[c*2+1];
    const float isq2 = 0.7071067811865476f;
#pragma unroll
    for (int w = 0; w < 4; w++) {
        float ay = (w & 1) ? a1 : a0, az = (w & 1) ? z1 : z0;
        float cy = cosf(ay*0.5f), sy = sinf(ay*0.5f);
        float cz = cosf(az*0.5f), sz = sinf(az*0.5f);
        float m00 = (cy-sy)*isq2, m01 = (cy+sy)*isq2;
        float m10 = (sy+cy)*isq2, m11 = (sy-cy)*isq2;
        gr[w][0][0]=m00*cz; gi[w][0][0]=-m00*sz;
        gr[w][0][1]=m01*cz; gi[w][0][1]=-m01*sz;
        gr[w][1][0]=m10*cz; gi[w][1][0]= m10*sz;
        gr[w][1][1]=m11*cz; gi[w][1][1]= m11*sz;
    }
    int P[16];
#pragma unroll
    for (int bb = 0; bb < 16; bb++) {
        int v = bb;
        if (v & 1) v ^= 8;
        if (v & 2) v ^= 1;
        if (v & 4) v ^= 2;
        if (v & 8) v ^= 4;
        P[bb] = v;
    }
    float acc[16];
#pragma unroll
    for (int j = 0; j < 16; j++) acc[j] = 0.f;
    for (int i = 0; i < 16; i++) {
        int r = P[i];
        float zi = (4 - 2 * __popc(i)) * 0.25f;
        int r0=(r>>3)&1, r1=(r>>2)&1, r2=(r>>1)&1, r3=r&1;
        float t2r[2], t2i[2];
        t2r[0]=gr[0][r0][0]; t2i[0]=gi[0][r0][0];
        t2r[1]=gr[0][r0][1]; t2i[1]=gi[0][r0][1];
        float t4r[4], t4i[4];
#pragma unroll
        for (int j0 = 0; j0 < 2; j0++)
#pragma unroll
            for (int j1 = 0; j1 < 2; j1++) {
                float br=gr[1][r1][j1], bi=gi[1][r1][j1];
                t4r[j0*2+j1]=t2r[j0]*br-t2i[j0]*bi;
                t4i[j0*2+j1]=t2r[j0]*bi+t2i[j0]*br;
            }
        float t8r[8], t8i[8];
#pragma unroll
        for (int j = 0; j < 4; j++)
#pragma unroll
            for (int j2 = 0; j2 < 2; j2++) {
                float br=gr[2][r2][j2], bi=gi[2][r2][j2];
                t8r[j*2+j2]=t4r[j]*br-t4i[j]*bi;
                t8i[j*2+j2]=t4r[j]*bi+t4i[j]*br;
            }
        float ur[16], ui[16];
#pragma unroll
        for (int j = 0; j < 8; j++)
#pragma unroll
            for (int j3 = 0; j3 < 2; j3++) {
                float br=gr[3][r3][j3], bi=gi[3][r3][j3];
                ur[j*2+j3]=t8r[j]*br-t8i[j]*bi;
                ui[j*2+j3]=t8r[j]*bi+t8i[j]*br;
            }
        float ukr = ur[k], uki = ui[k];
#pragma unroll
        for (int j = 0; j < 16; j++)
            acc[j] += zi * (ur[j]*ukr + ui[j]*uki);
    }
#pragma unroll
    for (int j = 0; j < 16; j++) A[c*256 + j*16 + k] = acc[j];
}

// ---------------- quantum stage + BN5 + ReLU (fused) -------------------------
__global__ __launch_bounds__(256) void quantum_kernel(
    const float* __restrict__ e4, const float* __restrict__ A,
    const float* __restrict__ g5, const float* __restrict__ b5,
    float* __restrict__ out)
{
    __shared__ float tile[35 * 37];
    __shared__ float As[256];
    const int bc = blockIdx.x, c = bc & 255, tid = threadIdx.x;
    for (int i = tid; i < 35 * 37; i += 256) tile[i] = 0.f;
    __syncthreads();
    const float* ep = e4 + (long)bc * 1024;
    for (int i = tid; i < 1024; i += 256) {
        int r = i >> 5, cc = i & 31;
        tile[(r + 1) * 37 + (cc + 1)] = ep[i];
    }
    if (tid < 256) As[tid] = A[c * 256 + tid];
    __syncthreads();
    const int y = tid >> 3, x4 = (tid & 7) * 4;
    float win[4][7];
#pragma unroll
    for (int r = 0; r < 4; r++)
#pragma unroll
        for (int cc = 0; cc < 7; cc++) win[r][cc] = tile[(y + r) * 37 + x4 + cc];
    float s[4] = {0.f, 0.f, 0.f, 0.f};
#pragma unroll
    for (int o = 0; o < 4; o++)
#pragma unroll
        for (int t = 0; t < 16; t++) {
            float v = win[t >> 2][(t & 3) + o];
            s[o] += v * v;
        }
    float quad[4] = {0.f, 0.f, 0.f, 0.f};
#pragma unroll
    for (int j = 0; j < 16; j++) {
        float t0 = 0.f, t1 = 0.f, t2 = 0.f, t3 = 0.f;
        int jr = j >> 2, jc = j & 3;
#pragma unroll
        for (int k = 0; k < 16; k++) {
            float a = As[j * 16 + k];
            int kr = k >> 2, kc = k & 3;
            t0 += a * win[kr][kc + 0];
            t1 += a * win[kr][kc + 1];
            t2 += a * win[kr][kc + 2];
            t3 += a * win[kr][kc + 3];
        }
        quad[0] += t0 * win[jr][jc + 0];
        quad[1] += t1 * win[jr][jc + 1];
        quad[2] += t2 * win[jr][jc + 2];
        quad[3] += t3 * win[jr][jc + 3];
    }
    const float sc = g5[c] * BN_INV, bb = b5[c];
    float4 v;
    v.x = fmaxf((0.5f*quad[0]/fmaxf(s[0],1e-24f)+0.5f)*sc+bb, 0.f);
    v.y = fmaxf((0.5f*quad[1]/fmaxf(s[1],1e-24f)+0.5f)*sc+bb, 0.f);
    v.z = fmaxf((0.5f*quad[2]/fmaxf(s[2],1e-24f)+0.5f)*sc+bb, 0.f);
    v.w = fmaxf((0.5f*quad[3]/fmaxf(s[3],1e-24f)+0.5f)*sc+bb, 0.f);
    *(float4*)(out + (long)bc * 1024 + y * 32 + x4) = v;
}

// -----------------------------------------------------------------------------
// dyn smem: conv2 52032, conv3 93824, conv4 94976
extern "C" void kernel_launch(void* const* d_in, const int* in_sizes, int n_in,
                              void* d_out, int out_size)
{
    (void)in_sizes; (void)n_in; (void)out_size;
    const float* x   = (const float*)d_in[0];
    const float* w1  = (const float*)d_in[1];
    const float* g1  = (const float*)d_in[2];
    const float* b1  = (const float*)d_in[3];
    const float* w2  = (const float*)d_in[4];
    const float* g2  = (const float*)d_in[5];
    const float* b2  = (const float*)d_in[6];
    const float* w3  = (const float*)d_in[7];
    const float* g3  = (const float*)d_in[8];
    const float* b3  = (const float*)d_in[9];
    const float* w4  = (const float*)d_in[10];
    const float* g4  = (const float*)d_in[11];
    const float* b4  = (const float*)d_in[12];
    const float* qw0 = (const float*)d_in[13];
    const float* qw1 = (const float*)d_in[14];
    const float* g5  = (const float*)d_in[15];
    const float* b5  = (const float*)d_in[16];

    float* out = (float*)d_out;
    float* e1 = out;
    float* e2 = out + 16777216;
    float* e3 = out + 25165824;
    float* o4 = out + 29360128;

    uint32_t *p1h, *p1l, *p2h, *p2l, *p3h, *p3l;
    uint16_t *B2h, *B2l, *B3h, *B3l, *B4h, *B4l;
    float *e4, *Ab;
    cudaGetSymbolAddress((void**)&p1h, g_p1h); cudaGetSymbolAddress((void**)&p1l, g_p1l);
    cudaGetSymbolAddress((void**)&p2h, g_p2h); cudaGetSymbolAddress((void**)&p2l, g_p2l);
    cudaGetSymbolAddress((void**)&p3h, g_p3h); cudaGetSymbolAddress((void**)&p3l, g_p3l);
    cudaGetSymbolAddress((void**)&B2h, g_B2h); cudaGetSymbolAddress((void**)&B2l, g_B2l);
    cudaGetSymbolAddress((void**)&B3h, g_B3h); cudaGetSymbolAddress((void**)&B3l, g_B3l);
    cudaGetSymbolAddress((void**)&B4h, g_B4h); cudaGetSymbolAddress((void**)&B4l, g_B4l);
    cudaGetSymbolAddress((void**)&e4, g_e4);   cudaGetSymbolAddress((void**)&Ab, g_A);

    cudaFuncSetAttribute(conv_mma_kernel, cudaFuncAttributeMaxDynamicSharedMemorySize, 94976);

    // conv1 -> e1 (fp32 exact)
    conv1_kernel<<<dim3(4, 16, 8), 256>>>(x, w1, g1, b1, e1);
    // weight packing (independent)
    pack_w_kernel<<<72, 256>>>(w2, B2h, B2l, 32, 32, 1, 18432);
    pack_w_kernel<<<288, 256>>>(w3, B3h, B3l, 64, 64, 1, 73728);
    pack_w_kernel<<<1152, 256>>>(w4, B4h, B4l, 128, 64, 2, 294912);
    // pool1: e1 (8,32,256,256) -> p1 NHWC 32ch bf16 hi/lo (128x128)
    pool_split_kernel<<<8192, 256>>>(e1, p1h, p1l, 32, 128, 128, 2097152);
    // conv2 -> e2 (8,64,128,128)
    conv_mma_kernel<<<dim3(128, 1, 8), 256, 52032>>>(
        (const uint4*)p1h, (const uint4*)p1l, (const uint4*)B2h, (const uint4*)B2l,
        g2, b2, e2, 128, 128, 7, 1, 32, 4, 1, 64);
    // pool2: e2 -> p2 NHWC 64ch (64x64)
    pool_split_kernel<<<4096, 256>>>(e2, p2h, p2l, 64, 64, 64, 1048576);
    // conv3 -> e3 (8,128,64,64)
    conv_mma_kernel<<<dim3(32, 2, 8), 256, 93824>>>(
        (const uint4*)p2h, (const uint4*)p2l, (const uint4*)B3h, (const uint4*)B3l,
        g3, b3, e3, 64, 64, 6, 2, 64, 8, 1, 128);
    // pool3: e3 -> p3 NHWC 128ch (32x32)
    pool_split_kernel<<<2048, 256>>>(e3, p3h, p3l, 128, 32, 32, 524288);
    // conv4 -> e4 (8,256,32,32)
    conv_mma_kernel<<<dim3(8, 4, 8), 256, 94976>>>(
        (const uint4*)p3h, (const uint4*)p3l, (const uint4*)B4h, (const uint4*)B4l,
        g4, b4, e4, 32, 32, 5, 4, 64, 16, 2, 256);
    // quantum
    build_A_kernel<<<16, 256>>>(qw0, qw1, Ab);
    quantum_kernel<<<2048, 256>>>(e4, Ab, g5, b5, o4);
}

// round 7
// speedup vs baseline: 2.1015x; 1.1589x over previous
#include <cuda_runtime.h>
#include <cuda_bf16.h>
#include <math.h>
#include <stdint.h>

#define BN_INV 0.9999950000374997f

// ---------------- scratch (device globals) -----------------------------------
__device__ __align__(16) uint32_t g_p1h[8*128*128*16], g_p1l[8*128*128*16];
__device__ __align__(16) uint32_t g_p2h[8*64*64*32],   g_p2l[8*64*64*32];
__device__ __align__(16) uint32_t g_p3h[8*32*32*64],   g_p3l[8*32*32*64];
__device__ __align__(16) uint16_t g_B2h[9*64*40],   g_B2l[9*64*40];
__device__ __align__(16) uint16_t g_B3h[18*64*72],  g_B3l[18*64*72];
__device__ __align__(16) uint16_t g_B4h[72*64*72],  g_B4l[72*64*72];
__device__ float g_e4[8*256*32*32];
__device__ float g_A [256*16*16];

// ---------------- helpers -----------------------------------------------------
__device__ __forceinline__ uint32_t smem_to_u32(const void* p) {
    uint32_t a;
    asm("{ .reg .u64 t; cvta.to.shared.u64 t, %1; cvt.u32.u64 %0, t; }" : "=r"(a) : "l"(p));
    return a;
}
#define LDSM4(r, a) \
    asm volatile("ldmatrix.sync.aligned.m8n8.x4.shared.b16 {%0,%1,%2,%3}, [%4];" \
        : "=r"((r)[0]), "=r"((r)[1]), "=r"((r)[2]), "=r"((r)[3]) : "r"(a))

__device__ __forceinline__ void mma16816(float* c, const uint32_t* a, uint32_t b0, uint32_t b1) {
    asm volatile(
        "mma.sync.aligned.m16n8k16.row.col.f32.bf16.bf16.f32 "
        "{%0,%1,%2,%3}, {%4,%5,%6,%7}, {%8,%9}, {%0,%1,%2,%3};"
        : "+f"(c[0]), "+f"(c[1]), "+f"(c[2]), "+f"(c[3])
        : "r"(a[0]), "r"(a[1]), "r"(a[2]), "r"(a[3]), "r"(b0), "r"(b1));
}

// split: hi = top-16 truncation of (a,b) packed; lo = rn(x - hi) packed bf16x2
__device__ __forceinline__ void split2(float a, float b, uint32_t& hi2, uint32_t& lo2) {
    uint32_t au = __float_as_uint(a), bu = __float_as_uint(b);
    hi2 = __byte_perm(au, bu, 0x7632);
    float la = a - __uint_as_float(au & 0xFFFF0000u);
    float lb = b - __uint_as_float(bu & 0xFFFF0000u);
    __nv_bfloat162 l2 = __floats2bfloat162_rn(la, lb);
    lo2 = *reinterpret_cast<uint32_t*>(&l2);
}

// ======================= conv1 + pool1 fused =================================
// conv1: 1->32ch, 256x256, BN+ReLU -> e1 (exact fp32 output)
// plus pool1 (2x2 max) emitted as NHWC bf16 hi/lo words directly.
__global__ __launch_bounds__(256) void conv1_pool_kernel(
    const float* __restrict__ x, const float* __restrict__ w,
    const float* __restrict__ g, const float* __restrict__ b,
    float* __restrict__ out, uint32_t* __restrict__ oh, uint32_t* __restrict__ ol)
{
    __shared__ float ws[288], ss[32], bs[32];
    __shared__ float tile[18][66];
    const int tid = threadIdx.x;
    for (int i = tid; i < 288; i += 256) ws[i] = w[i];
    if (tid < 32) { ss[tid] = g[tid] * BN_INV; bs[tid] = b[tid]; }
    const int n = blockIdx.z, y0 = blockIdx.y * 16, x0 = blockIdx.x * 64;
    const float* xp = x + (long)n * 65536;
    for (int i = tid; i < 18 * 66; i += 256) {
        int r = i / 66, c = i % 66, yy = y0 - 1 + r, xx = x0 - 1 + c;
        tile[r][c] = (yy >= 0 && yy < 256 && xx >= 0 && xx < 256) ? xp[yy * 256 + xx] : 0.f;
    }
    __syncthreads();
    const int tx = tid & 15, ty = tid >> 4;
    float win[3][6];
#pragma unroll
    for (int r = 0; r < 3; r++)
#pragma unroll
        for (int c = 0; c < 6; c++) win[r][c] = tile[ty + r][tx * 4 + c];
    float* op = out + (long)n * 32 * 65536 + (y0 + ty) * 256 + x0 + tx * 4;

    const bool lowlane = ((tid & 31) < 16);
    const int yp = (y0 >> 1) + (ty >> 1);
    const int xp0 = (x0 >> 1) + tx * 2;
    const long pbase = (((long)n * 128 + yp) * 128 + xp0) * 16;

#pragma unroll
    for (int cb = 0; cb < 4; cb++) {
        float h0s[8], h1s[8];
#pragma unroll
        for (int c = 0; c < 8; c++) {
            int ch = cb * 8 + c;
            float acc0 = 0.f, acc1 = 0.f, acc2 = 0.f, acc3 = 0.f;
#pragma unroll
            for (int ky = 0; ky < 3; ky++)
#pragma unroll
                for (int kx = 0; kx < 3; kx++) {
                    float wv = ws[ch * 9 + ky * 3 + kx];
                    acc0 += wv * win[ky][kx + 0];
                    acc1 += wv * win[ky][kx + 1];
                    acc2 += wv * win[ky][kx + 2];
                    acc3 += wv * win[ky][kx + 3];
                }
            float s = ss[ch], bb = bs[ch];
            float4 v;
            v.x = fmaxf(acc0 * s + bb, 0.f); v.y = fmaxf(acc1 * s + bb, 0.f);
            v.z = fmaxf(acc2 * s + bb, 0.f); v.w = fmaxf(acc3 * s + bb, 0.f);
            *(float4*)(op + (long)ch * 65536) = v;
            h0s[c] = fmaxf(v.x, v.y);
            h1s[c] = fmaxf(v.z, v.w);
        }
        // 2x2 pool: combine row pairs via shfl (ty even <-> ty odd in same warp)
#pragma unroll
        for (int c = 0; c < 8; c++) {
            float q0 = __shfl_xor_sync(0xffffffffu, h0s[c], 16);
            float q1 = __shfl_xor_sync(0xffffffffu, h1s[c], 16);
            h0s[c] = fmaxf(h0s[c], q0);
            h1s[c] = fmaxf(h1s[c], q1);
        }
        if (lowlane) {
            uint4 hv0, lv0, hv1, lv1;
            split2(h0s[0], h0s[1], hv0.x, lv0.x); split2(h0s[2], h0s[3], hv0.y, lv0.y);
            split2(h0s[4], h0s[5], hv0.z, lv0.z); split2(h0s[6], h0s[7], hv0.w, lv0.w);
            split2(h1s[0], h1s[1], hv1.x, lv1.x); split2(h1s[2], h1s[3], hv1.y, lv1.y);
            split2(h1s[4], h1s[5], hv1.z, lv1.z); split2(h1s[6], h1s[7], hv1.w, lv1.w);
            *(uint4*)(oh + pbase + cb * 4)      = hv0;
            *(uint4*)(ol + pbase + cb * 4)      = lv0;
            *(uint4*)(oh + pbase + 16 + cb * 4) = hv1;
            *(uint4*)(ol + pbase + 16 + cb * 4) = lv1;
        }
    }
}

// ======== pool: NCHW fp32 -> NHWC bf16 hi/lo words (2 channels per word) ======
__global__ __launch_bounds__(256) void pool_split_kernel(
    const float* __restrict__ in, uint32_t* __restrict__ oh, uint32_t* __restrict__ ol,
    int C, int Ho, int Wo, int total)
{
    int t = blockIdx.x * 256 + threadIdx.x;
    if (t >= total) return;
    const int CW = C >> 1;
    int cw = t % CW; int r = t / CW;
    int x = r % Wo; r /= Wo;
    int y = r % Ho; int n = r / Ho;
    const int Wi = Wo * 2, Hi = Ho * 2;
    long base = (((long)n * C + 2 * cw) * Hi + 2 * y) * Wi + 2 * x;
    long pl = (long)Hi * Wi;
    float a = fmaxf(fmaxf(in[base], in[base + 1]), fmaxf(in[base + Wi], in[base + Wi + 1]));
    float b = fmaxf(fmaxf(in[base + pl], in[base + pl + 1]),
                    fmaxf(in[base + pl + Wi], in[base + pl + Wi + 1]));
    uint32_t hw, lw;
    split2(a, b, hw, lw);
    long o = (((long)n * Ho + y) * Wo + x) * CW + cw;
    oh[o] = hw; ol[o] = lw;
}

// ======== pack all weights in one launch ======================================
__device__ __forceinline__ void pack_one(const float* __restrict__ w, int e,
                                         int Cin, int K, int nkc,
                                         uint16_t* __restrict__ oh, uint16_t* __restrict__ ol)
{
    const int rw2 = K + 8;
    int ic = e % K;
    int t = e / K;
    int r = t % 64;
    int blk = t / 64;
    int kc = blk % nkc, t2 = blk / nkc;
    int pos = t2 % 9, ocb = t2 / 9;
    int icg = kc * 64 + ic, ocg = ocb * 64 + r;
    float v = w[((long)ocg * Cin + icg) * 9 + pos];
    uint32_t u = __float_as_uint(v);
    float vl = v - __uint_as_float(u & 0xFFFF0000u);
    long idx = (long)blk * 64 * rw2 + r * rw2 + ic;
    oh[idx] = (uint16_t)(u >> 16);
    ol[idx] = __bfloat16_as_ushort(__float2bfloat16(vl));
}

__global__ void pack_all_kernel(
    const float* __restrict__ w2, const float* __restrict__ w3, const float* __restrict__ w4,
    uint16_t* __restrict__ B2h, uint16_t* __restrict__ B2l,
    uint16_t* __restrict__ B3h, uint16_t* __restrict__ B3l,
    uint16_t* __restrict__ B4h, uint16_t* __restrict__ B4l)
{
    int e = blockIdx.x * 256 + threadIdx.x;
    if (e < 18432)       pack_one(w2, e,          32,  32, 1, B2h, B2l);
    else if (e < 92160)  pack_one(w3, e - 18432,  64,  64, 1, B3h, B3l);
    else if (e < 387072) pack_one(w4, e - 92160, 128,  64, 2, B4h, B4l);
}

// ======== mma.sync implicit-GEMM conv (cp.async gathers) ======================
// M=128 pixels x N=64 oc per CTA; per (ky,kc): gather A once (rpt segments of
// W+2 rows), load 3 kx B blocks, run 3x(K/16) MMA phases; smem-staged epilogue.
__global__ __launch_bounds__(256) void conv_mma_kernel(
    const uint4* __restrict__ inh, const uint4* __restrict__ inl,
    const uint4* __restrict__ Bh, const uint4* __restrict__ Bl,
    const float* __restrict__ g, const float* __restrict__ b,
    float* __restrict__ out,
    int H, int W, int Wsh, int rpt, int K, int CW4, int nkc, int Cout)
{
    extern __shared__ char sm[];
    const int strideA = K * 2 + 16;
    const int Wp2 = W + 2;
    const int rowsA = rpt * Wp2;
    const int hsh = (K == 32) ? 2 : 3;       // uint4 per row per array = K/8
    const int hc4m = (K >> 3) - 1;
    const int Bw4 = 4 * strideA;             // uint4 per tap per array
    const int tid = threadIdx.x;
    const int ocb = blockIdx.y, n = blockIdx.z;
    const int y0 = blockIdx.x * rpt;

    char* Bls_end_marker; (void)Bls_end_marker;
    float* ss = (float*)(sm + (size_t)rowsA * strideA * 2 + (size_t)3 * 64 * strideA * 2);
    float* bs = ss + 64;
    float* stage = (float*)sm;               // reused after final sync

    if (tid < 64) { ss[tid] = g[ocb * 64 + tid] * BN_INV; bs[tid] = b[ocb * 64 + tid]; }

    const uint32_t AhU = smem_to_u32(sm);
    const uint32_t AlU = AhU + rowsA * strideA;
    const uint32_t BhU = AlU + rowsA * strideA;
    const uint32_t BlU = BhU + 3 * 64 * strideA;

    const int lane = tid & 31, warp = tid >> 5;
    const int wm = warp & 3, wn = warp >> 2;
    const int mbase = wm * 32, nbase = wn * 32;

    // ldmatrix lane geometry
    const int arow = lane & 15, acol = (lane >> 4) * 16;
    const int brow = (lane & 7) + ((lane >> 4) << 3), bcol = ((lane >> 3) & 1) * 16;

    // per-thread A row base for each mt (kx=0): seg*(W+2) + px
    int aRowBase[2];
#pragma unroll
    for (int mt = 0; mt < 2; mt++) {
        int m = mbase + mt * 16 + arow;
        aRowBase[mt] = (m >> Wsh) * Wp2 + (m & (W - 1));
    }

    float acc[2][4][4];
#pragma unroll
    for (int i = 0; i < 2; i++)
#pragma unroll
        for (int j = 0; j < 4; j++)
#pragma unroll
            for (int k = 0; k < 4; k++) acc[i][j][k] = 0.f;

    const int totA = rowsA << hsh;

    for (int ky = 0; ky < 3; ky++) {
        for (int kc = 0; kc < nkc; kc++) {
            __syncthreads();   // prior MMA reads done before overwrite
            // ---- A gather via cp.async (zero-fill halo) ----
            for (int i = tid; i < totA; i += 256) {
                int row = i >> hsh, j = i & hc4m;
                int seg = row / Wp2;
                int px = row - seg * Wp2 - 1;
                int py = y0 + seg + ky - 1;
                bool ok = ((unsigned)px < (unsigned)W) && ((unsigned)py < (unsigned)H);
                long src = (((long)n * H + py) * W + px) * CW4 + kc * 8 + j;
                uint32_t dA = AhU + (uint32_t)(row * strideA + j * 16);
                int sz = ok ? 16 : 0;
                asm volatile("cp.async.cg.shared.global [%0], [%1], 16, %2;"
                             :: "r"(dA), "l"(inh + src), "r"(sz) : "memory");
                asm volatile("cp.async.cg.shared.global [%0], [%1], 16, %2;"
                             :: "r"(dA + (uint32_t)(rowsA * strideA)), "l"(inl + src), "r"(sz) : "memory");
            }
            // ---- B: 3 kx taps for this (ky,kc) ----
            {
                const int blk0 = (ocb * 9 + ky * 3) * nkc + kc;
                for (int i = tid; i < 3 * Bw4; i += 256) {
                    int tap = i / Bw4, r = i - tap * Bw4;
                    long gsrc = (long)(blk0 + tap * nkc) * Bw4 + r;
                    uint32_t dB = BhU + (uint32_t)i * 16;
                    asm volatile("cp.async.cg.shared.global [%0], [%1], 16;"
                                 :: "r"(dB), "l"(Bh + gsrc) : "memory");
                    asm volatile("cp.async.cg.shared.global [%0], [%1], 16;"
                                 :: "r"(dB + (uint32_t)(3 * 64 * strideA)), "l"(Bl + gsrc) : "memory");
                }
            }
            asm volatile("cp.async.commit_group;" ::: "memory");
            asm volatile("cp.async.wait_group 0;" ::: "memory");
            __syncthreads();
            // ---- MMA: 3 kx taps x K/16 ----
            for (int kx = 0; kx < 3; kx++) {
                for (int k16 = 0; k16 < (K >> 4); k16++) {
                    uint32_t ah[2][4], al[2][4], bh[2][4], bl[2][4];
#pragma unroll
                    for (int mt = 0; mt < 2; mt++) {
                        uint32_t aaddr = AhU + (uint32_t)(aRowBase[mt] + kx) * strideA
                                       + k16 * 32 + acol;
                        LDSM4(ah[mt], aaddr);
                        LDSM4(al[mt], aaddr + (uint32_t)(rowsA * strideA));
                    }
#pragma unroll
                    for (int g2 = 0; g2 < 2; g2++) {
                        uint32_t baddr = BhU + (uint32_t)(kx * 64 + nbase + g2 * 16 + brow) * strideA
                                       + k16 * 32 + bcol;
                        LDSM4(bh[g2], baddr);
                        LDSM4(bl[g2], baddr + (uint32_t)(3 * 64 * strideA));
                    }
#pragma unroll
                    for (int mt = 0; mt < 2; mt++)
#pragma unroll
                        for (int nt = 0; nt < 4; nt++) {
                            const int g2 = nt >> 1, pr = (nt & 1) * 2;
                            mma16816(acc[mt][nt], ah[mt], bh[g2][pr], bh[g2][pr + 1]);
                            mma16816(acc[mt][nt], ah[mt], bl[g2][pr], bl[g2][pr + 1]);
                            mma16816(acc[mt][nt], al[mt], bh[g2][pr], bh[g2][pr + 1]);
                        }
                }
            }
        }
    }

    // ---- epilogue: stage in smem ([oc][pixel], stride 132), coalesced stores --
    __syncthreads();
    {
        const int r0 = lane >> 2, cpair = (lane & 3) * 2;
#pragma unroll
        for (int mt = 0; mt < 2; mt++) {
            const int m1 = mbase + mt * 16 + r0, m2 = m1 + 8;
#pragma unroll
            for (int nt = 0; nt < 4; nt++) {
                const int nc = nbase + nt * 8 + cpair;
                stage[nc * 132 + m1]       = acc[mt][nt][0];
                stage[(nc + 1) * 132 + m1] = acc[mt][nt][1];
                stage[nc * 132 + m2]       = acc[mt][nt][2];
                stage[(nc + 1) * 132 + m2] = acc[mt][nt][3];
            }
        }
    }
    __syncthreads();
    {
        const long HW = (long)H * W;
        const long obase = ((long)n * Cout + ocb * 64) * HW;
        for (int i = tid; i < 8192; i += 256) {
            int oc = i >> 7, p = i & 127;
            int y = y0 + (p >> Wsh), x = p & (W - 1);
            float v = fmaxf(stage[oc * 132 + p] * ss[oc] + bs[oc], 0.f);
            out[obase + (long)oc * HW + (long)y * W + x] = v;
        }
    }
}

// ---------------- build per-channel quadratic form A = Re(U^H diag(zbar) U) --
__global__ void build_A_kernel(const float* __restrict__ w0,
                               const float* __restrict__ w1,
                               float* __restrict__ A)
{
    int t = blockIdx.x * blockDim.x + threadIdx.x;
    if (t >= 256 * 16) return;
    int c = t >> 4, k = t & 15;
    float gr[4][2][2], gi[4][2][2];
    float a0 = w0[c*2+0], a1 = w0[c*2+1], z0 = w1[c*2+0], z1 = w1[c*2+1];
    const float isq2 = 0.7071067811865476f;
#pragma unroll
    for (int w = 0; w < 4; w++) {
        float ay = (w & 1) ? a1 : a0, az = (w & 1) ? z1 : z0;
        float cy = cosf(ay*0.5f), sy = sinf(ay*0.5f);
        float cz = cosf(az*0.5f), sz = sinf(az*0.5f);
        float m00 = (cy-sy)*isq2, m01 = (cy+sy)*isq2;
        float m10 = (sy+cy)*isq2, m11 = (sy-cy)*isq2;
        gr[w][0][0]=m00*cz; gi[w][0][0]=-m00*sz;
        gr[w][0][1]=m01*cz; gi[w][0][1]=-m01*sz;
        gr[w][1][0]=m10*cz; gi[w][1][0]= m10*sz;
        gr[w][1][1]=m11*cz; gi[w][1][1]= m11*sz;
    }
    int P[16];
#pragma unroll
    for (int bb = 0; bb < 16; bb++) {
        int v = bb;
        if (v & 1) v ^= 8;
        if (v & 2) v ^= 1;
        if (v & 4) v ^= 2;
        if (v & 8) v ^= 4;
        P[bb] = v;
    }
    float acc[16];
#pragma unroll
    for (int j = 0; j < 16; j++) acc[j] = 0.f;
    for (int i = 0; i < 16; i++) {
        int r = P[i];
        float zi = (4 - 2 * __popc(i)) * 0.25f;
        int r0=(r>>3)&1, r1=(r>>2)&1, r2=(r>>1)&1, r3=r&1;
        float t2r[2], t2i[2];
        t2r[0]=gr[0][r0][0]; t2i[0]=gi[0][r0][0];
        t2r[1]=gr[0][r0][1]; t2i[1]=gi[0][r0][1];
        float t4r[4], t4i[4];
#pragma unroll
        for (int j0 = 0; j0 < 2; j0++)
#pragma unroll
            for (int j1 = 0; j1 < 2; j1++) {
                float br=gr[1][r1][j1], bi=gi[1][r1][j1];
                t4r[j0*2+j1]=t2r[j0]*br-t2i[j0]*bi;
                t4i[j0*2+j1]=t2r[j0]*bi+t2i[j0]*br;
            }
        float t8r[8], t8i[8];
#pragma unroll
        for (int j = 0; j < 4; j++)
#pragma unroll
            for (int j2 = 0; j2 < 2; j2++) {
                float br=gr[2][r2][j2], bi=gi[2][r2][j2];
                t8r[j*2+j2]=t4r[j]*br-t4i[j]*bi;
                t8i[j*2+j2]=t4r[j]*bi+t4i[j]*br;
            }
        float ur[16], ui[16];
#pragma unroll
        for (int j = 0; j < 8; j++)
#pragma unroll
            for (int j3 = 0; j3 < 2; j3++) {
                float br=gr[3][r3][j3], bi=gi[3][r3][j3];
                ur[j*2+j3]=t8r[j]*br-t8i[j]*bi;
                ui[j*2+j3]=t8r[j]*bi+t8i[j]*br;
            }
        float ukr = ur[k], uki = ui[k];
#pragma unroll
        for (int j = 0; j < 16; j++)
            acc[j] += zi * (ur[j]*ukr + ui[j]*uki);
    }
#pragma unroll
    for (int j = 0; j < 16; j++) A[c*256 + j*16 + k] = acc[j];
}

// ---------------- quantum stage + BN5 + ReLU (fused) -------------------------
__global__ __launch_bounds__(256) void quantum_kernel(
    const float* __restrict__ e4, const float* __restrict__ A,
    const float* __restrict__ g5, const float* __restrict__ b5,
    float* __restrict__ out)
{
    __shared__ float tile[35 * 37];
    __shared__ float As[256];
    const int bc = blockIdx.x, c = bc & 255, tid = threadIdx.x;
    for (int i = tid; i < 35 * 37; i += 256) tile[i] = 0.f;
    __syncthreads();
    const float* ep = e4 + (long)bc * 1024;
    for (int i = tid; i < 1024; i += 256) {
        int r = i >> 5, cc = i & 31;
        tile[(r + 1) * 37 + (cc + 1)] = ep[i];
    }
    if (tid < 256) As[tid] = A[c * 256 + tid];
    __syncthreads();
    const int y = tid >> 3, x4 = (tid & 7) * 4;
    float win[4][7];
#pragma unroll
    for (int r = 0; r < 4; r++)
#pragma unroll
        for (int cc = 0; cc < 7; cc++) win[r][cc] = tile[(y + r) * 37 + x4 + cc];
    float s[4] = {0.f, 0.f, 0.f, 0.f};
#pragma unroll
    for (int o = 0; o < 4; o++)
#pragma unroll
        for (int t = 0; t < 16; t++) {
            float v = win[t >> 2][(t & 3) + o];
            s[o] += v * v;
        }
    float quad[4] = {0.f, 0.f, 0.f, 0.f};
#pragma unroll
    for (int j = 0; j < 16; j++) {
        float t0 = 0.f, t1 = 0.f, t2 = 0.f, t3 = 0.f;
        int jr = j >> 2, jc = j & 3;
#pragma unroll
        for (int k = 0; k < 16; k++) {
            float a = As[j * 16 + k];
            int kr = k >> 2, kc = k & 3;
            t0 += a * win[kr][kc + 0];
            t1 += a * win[kr][kc + 1];
            t2 += a * win[kr][kc + 2];
            t3 += a * win[kr][kc + 3];
        }
        quad[0] += t0 * win[jr][jc + 0];
        quad[1] += t1 * win[jr][jc + 1];
        quad[2] += t2 * win[jr][jc + 2];
        quad[3] += t3 * win[jr][jc + 3];
    }
    const float sc = g5[c] * BN_INV, bb = b5[c];
    float4 v;
    v.x = fmaxf((0.5f*quad[0]/fmaxf(s[0],1e-24f)+0.5f)*sc+bb, 0.f);
    v.y = fmaxf((0.5f*quad[1]/fmaxf(s[1],1e-24f)+0.5f)*sc+bb, 0.f);
    v.z = fmaxf((0.5f*quad[2]/fmaxf(s[2],1e-24f)+0.5f)*sc+bb, 0.f);
    v.w = fmaxf((0.5f*quad[3]/fmaxf(s[3],1e-24f)+0.5f)*sc+bb, 0.f);
    *(float4*)(out + (long)bc * 1024 + y * 32 + x4) = v;
}

// -----------------------------------------------------------------------------
// dyn smem: conv2 52032, conv3 93824, conv4 94976
extern "C" void kernel_launch(void* const* d_in, const int* in_sizes, int n_in,
                              void* d_out, int out_size)
{
    (void)in_sizes; (void)n_in; (void)out_size;
    const float* x   = (const float*)d_in[0];
    const float* w1  = (const float*)d_in[1];
    const float* g1  = (const float*)d_in[2];
    const float* b1  = (const float*)d_in[3];
    const float* w2  = (const float*)d_in[4];
    const float* g2  = (const float*)d_in[5];
    const float* b2  = (const float*)d_in[6];
    const float* w3  = (const float*)d_in[7];
    const float* g3  = (const float*)d_in[8];
    const float* b3  = (const float*)d_in[9];
    const float* w4  = (const float*)d_in[10];
    const float* g4  = (const float*)d_in[11];
    const float* b4  = (const float*)d_in[12];
    const float* qw0 = (const float*)d_in[13];
    const float* qw1 = (const float*)d_in[14];
    const float* g5  = (const float*)d_in[15];
    const float* b5  = (const float*)d_in[16];

    float* out = (float*)d_out;
    float* e1 = out;
    float* e2 = out + 16777216;
    float* e3 = out + 25165824;
    float* o4 = out + 29360128;

    uint32_t *p1h, *p1l, *p2h, *p2l, *p3h, *p3l;
    uint16_t *B2h, *B2l, *B3h, *B3l, *B4h, *B4l;
    float *e4, *Ab;
    cudaGetSymbolAddress((void**)&p1h, g_p1h); cudaGetSymbolAddress((void**)&p1l, g_p1l);
    cudaGetSymbolAddress((void**)&p2h, g_p2h); cudaGetSymbolAddress((void**)&p2l, g_p2l);
    cudaGetSymbolAddress((void**)&p3h, g_p3h); cudaGetSymbolAddress((void**)&p3l, g_p3l);
    cudaGetSymbolAddress((void**)&B2h, g_B2h); cudaGetSymbolAddress((void**)&B2l, g_B2l);
    cudaGetSymbolAddress((void**)&B3h, g_B3h); cudaGetSymbolAddress((void**)&B3l, g_B3l);
    cudaGetSymbolAddress((void**)&B4h, g_B4h); cudaGetSymbolAddress((void**)&B4l, g_B4l);
    cudaGetSymbolAddress((void**)&e4, g_e4);   cudaGetSymbolAddress((void**)&Ab, g_A);

    cudaFuncSetAttribute(conv_mma_kernel, cudaFuncAttributeMaxDynamicSharedMemorySize, 94976);

    // conv1 + pool1 fused -> e1, p1
    conv1_pool_kernel<<<dim3(4, 16, 8), 256>>>(x, w1, g1, b1, e1, p1h, p1l);
    // weight packing (single launch)
    pack_all_kernel<<<1512, 256>>>(w2, w3, w4, B2h, B2l, B3h, B3l, B4h, B4l);
    // conv2 -> e2 (8,64,128,128)
    conv_mma_kernel<<<dim3(128, 1, 8), 256, 52032>>>(
        (const uint4*)p1h, (const uint4*)p1l, (const uint4*)B2h, (const uint4*)B2l,
        g2, b2, e2, 128, 128, 7, 1, 32, 4, 1, 64);
    // pool2: e2 -> p2 NHWC 64ch (64x64)
    pool_split_kernel<<<4096, 256>>>(e2, p2h, p2l, 64, 64, 64, 1048576);
    // conv3 -> e3 (8,128,64,64)
    conv_mma_kernel<<<dim3(32, 2, 8), 256, 93824>>>(
        (const uint4*)p2h, (const uint4*)p2l, (const uint4*)B3h, (const uint4*)B3l,
        g3, b3, e3, 64, 64, 6, 2, 64, 8, 1, 128);
    // pool3: e3 -> p3 NHWC 128ch (32x32)
    pool_split_kernel<<<2048, 256>>>(e3, p3h, p3l, 128, 32, 32, 524288);
    // conv4 -> e4 (8,256,32,32)
    conv_mma_kernel<<<dim3(8, 4, 8), 256, 94976>>>(
        (const uint4*)p3h, (const uint4*)p3l, (const uint4*)B4h, (const uint4*)B4l,
        g4, b4, e4, 32, 32, 5, 4, 64, 16, 2, 256);
    // quantum
    build_A_kernel<<<16, 256>>>(qw0, qw1, Ab);
    quantum_kernel<<<2048, 256>>>(e4, Ab, g5, b5, o4);
}

// round 8
// speedup vs baseline: 2.5132x; 1.1959x over previous
#include <cuda_runtime.h>
#include <cuda_bf16.h>
#include <math.h>
#include <stdint.h>

#define BN_INV 0.9999950000374997f

// ---------------- scratch (device globals) -----------------------------------
__device__ __align__(16) uint32_t g_p1h[8*128*128*16], g_p1l[8*128*128*16];
__device__ __align__(16) uint32_t g_p2h[8*64*64*32],   g_p2l[8*64*64*32];
__device__ __align__(16) uint32_t g_p3h[8*32*32*64],   g_p3l[8*32*32*64];
__device__ __align__(16) uint16_t g_B2h[9*64*40],   g_B2l[9*64*40];
__device__ __align__(16) uint16_t g_B3h[18*64*72],  g_B3l[18*64*72];
__device__ __align__(16) uint16_t g_B4h[72*64*72],  g_B4l[72*64*72];
__device__ float g_e4[8*256*32*32];
__device__ float g_A [256*16*16];

// ---------------- helpers -----------------------------------------------------
__device__ __forceinline__ uint32_t smem_to_u32(const void* p) {
    uint32_t a;
    asm("{ .reg .u64 t; cvta.to.shared.u64 t, %1; cvt.u32.u64 %0, t; }" : "=r"(a) : "l"(p));
    return a;
}
#define LDSM4(r, a) \
    asm volatile("ldmatrix.sync.aligned.m8n8.x4.shared.b16 {%0,%1,%2,%3}, [%4];" \
        : "=r"((r)[0]), "=r"((r)[1]), "=r"((r)[2]), "=r"((r)[3]) : "r"(a))

__device__ __forceinline__ void mma16816(float* c, const uint32_t* a, uint32_t b0, uint32_t b1) {
    asm volatile(
        "mma.sync.aligned.m16n8k16.row.col.f32.bf16.bf16.f32 "
        "{%0,%1,%2,%3}, {%4,%5,%6,%7}, {%8,%9}, {%0,%1,%2,%3};"
        : "+f"(c[0]), "+f"(c[1]), "+f"(c[2]), "+f"(c[3])
        : "r"(a[0]), "r"(a[1]), "r"(a[2]), "r"(a[3]), "r"(b0), "r"(b1));
}

// split: hi = top-16 truncation of (a,b) packed; lo = rn(x - hi) packed bf16x2
__device__ __forceinline__ void split2(float a, float b, uint32_t& hi2, uint32_t& lo2) {
    uint32_t au = __float_as_uint(a), bu = __float_as_uint(b);
    hi2 = __byte_perm(au, bu, 0x7632);
    float la = a - __uint_as_float(au & 0xFFFF0000u);
    float lb = b - __uint_as_float(bu & 0xFFFF0000u);
    __nv_bfloat162 l2 = __floats2bfloat162_rn(la, lb);
    lo2 = *reinterpret_cast<uint32_t*>(&l2);
}

// ======================= conv1 + pool1 fused =================================
__global__ __launch_bounds__(256) void conv1_pool_kernel(
    const float* __restrict__ x, const float* __restrict__ w,
    const float* __restrict__ g, const float* __restrict__ b,
    float* __restrict__ out, uint32_t* __restrict__ oh, uint32_t* __restrict__ ol)
{
    __shared__ float ws[288], ss[32], bs[32];
    __shared__ float tile[18][66];
    const int tid = threadIdx.x;
    for (int i = tid; i < 288; i += 256) ws[i] = w[i];
    if (tid < 32) { ss[tid] = g[tid] * BN_INV; bs[tid] = b[tid]; }
    const int n = blockIdx.z, y0 = blockIdx.y * 16, x0 = blockIdx.x * 64;
    const float* xp = x + (long)n * 65536;
    for (int i = tid; i < 18 * 66; i += 256) {
        int r = i / 66, c = i % 66, yy = y0 - 1 + r, xx = x0 - 1 + c;
        tile[r][c] = (yy >= 0 && yy < 256 && xx >= 0 && xx < 256) ? xp[yy * 256 + xx] : 0.f;
    }
    __syncthreads();
    const int tx = tid & 15, ty = tid >> 4;
    float win[3][6];
#pragma unroll
    for (int r = 0; r < 3; r++)
#pragma unroll
        for (int c = 0; c < 6; c++) win[r][c] = tile[ty + r][tx * 4 + c];
    float* op = out + (long)n * 32 * 65536 + (y0 + ty) * 256 + x0 + tx * 4;

    const bool lowlane = ((tid & 31) < 16);
    const int yp = (y0 >> 1) + (ty >> 1);
    const int xp0 = (x0 >> 1) + tx * 2;
    const long pbase = (((long)n * 128 + yp) * 128 + xp0) * 16;

#pragma unroll
    for (int cb = 0; cb < 4; cb++) {
        float h0s[8], h1s[8];
#pragma unroll
        for (int c = 0; c < 8; c++) {
            int ch = cb * 8 + c;
            float acc0 = 0.f, acc1 = 0.f, acc2 = 0.f, acc3 = 0.f;
#pragma unroll
            for (int ky = 0; ky < 3; ky++)
#pragma unroll
                for (int kx = 0; kx < 3; kx++) {
                    float wv = ws[ch * 9 + ky * 3 + kx];
                    acc0 += wv * win[ky][kx + 0];
                    acc1 += wv * win[ky][kx + 1];
                    acc2 += wv * win[ky][kx + 2];
                    acc3 += wv * win[ky][kx + 3];
                }
            float s = ss[ch], bb = bs[ch];
            float4 v;
            v.x = fmaxf(acc0 * s + bb, 0.f); v.y = fmaxf(acc1 * s + bb, 0.f);
            v.z = fmaxf(acc2 * s + bb, 0.f); v.w = fmaxf(acc3 * s + bb, 0.f);
            *(float4*)(op + (long)ch * 65536) = v;
            h0s[c] = fmaxf(v.x, v.y);
            h1s[c] = fmaxf(v.z, v.w);
        }
#pragma unroll
        for (int c = 0; c < 8; c++) {
            float q0 = __shfl_xor_sync(0xffffffffu, h0s[c], 16);
            float q1 = __shfl_xor_sync(0xffffffffu, h1s[c], 16);
            h0s[c] = fmaxf(h0s[c], q0);
            h1s[c] = fmaxf(h1s[c], q1);
        }
        if (lowlane) {
            uint4 hv0, lv0, hv1, lv1;
            split2(h0s[0], h0s[1], hv0.x, lv0.x); split2(h0s[2], h0s[3], hv0.y, lv0.y);
            split2(h0s[4], h0s[5], hv0.z, lv0.z); split2(h0s[6], h0s[7], hv0.w, lv0.w);
            split2(h1s[0], h1s[1], hv1.x, lv1.x); split2(h1s[2], h1s[3], hv1.y, lv1.y);
            split2(h1s[4], h1s[5], hv1.z, lv1.z); split2(h1s[6], h1s[7], hv1.w, lv1.w);
            *(uint4*)(oh + pbase + cb * 4)      = hv0;
            *(uint4*)(ol + pbase + cb * 4)      = lv0;
            *(uint4*)(oh + pbase + 16 + cb * 4) = hv1;
            *(uint4*)(ol + pbase + 16 + cb * 4) = lv1;
        }
    }
}

// ======== pack all weights in one launch ======================================
__device__ __forceinline__ void pack_one(const float* __restrict__ w, int e,
                                         int Cin, int K, int nkc,
                                         uint16_t* __restrict__ oh, uint16_t* __restrict__ ol)
{
    const int rw2 = K + 8;
    int ic = e % K;
    int t = e / K;
    int r = t % 64;
    int blk = t / 64;
    int kc = blk % nkc, t2 = blk / nkc;
    int pos = t2 % 9, ocb = t2 / 9;
    int icg = kc * 64 + ic, ocg = ocb * 64 + r;
    float v = w[((long)ocg * Cin + icg) * 9 + pos];
    uint32_t u = __float_as_uint(v);
    float vl = v - __uint_as_float(u & 0xFFFF0000u);
    long idx = (long)blk * 64 * rw2 + r * rw2 + ic;
    oh[idx] = (uint16_t)(u >> 16);
    ol[idx] = __bfloat16_as_ushort(__float2bfloat16(vl));
}

__global__ void pack_all_kernel(
    const float* __restrict__ w2, const float* __restrict__ w3, const float* __restrict__ w4,
    uint16_t* __restrict__ B2h, uint16_t* __restrict__ B2l,
    uint16_t* __restrict__ B3h, uint16_t* __restrict__ B3l,
    uint16_t* __restrict__ B4h, uint16_t* __restrict__ B4l)
{
    int e = blockIdx.x * 256 + threadIdx.x;
    if (e < 18432)       pack_one(w2, e,          32,  32, 1, B2h, B2l);
    else if (e < 92160)  pack_one(w3, e - 18432,  64,  64, 1, B3h, B3l);
    else if (e < 387072) pack_one(w4, e - 92160, 128,  64, 2, B4h, B4l);
}

// ======== mma.sync implicit-GEMM conv + fused 2x2 pool ========================
// CTA tile: rpt rows x TW cols (rpt*TW=128 pixels), N=64 oc.
// Per (ky,kc): cp.async-gather A once (rpt segments of TW+2), 3 kx B blocks,
// 3x(K/16) MMA phases. Epilogue: smem stage -> coalesced NCHW out; if ph!=0
// and rpt==2, also emit pooled NHWC bf16 hi/lo (maxpool after BN+ReLU).
__global__ __launch_bounds__(256) void conv_mma_kernel(
    const uint4* __restrict__ inh, const uint4* __restrict__ inl,
    const uint4* __restrict__ Bh, const uint4* __restrict__ Bl,
    const float* __restrict__ g, const float* __restrict__ b,
    float* __restrict__ out,
    int H, int W, int TWsh, int rpt, int K, int CW4, int nkc, int Cout, int xstrips,
    uint32_t* __restrict__ ph, uint32_t* __restrict__ pl, int poolCW)
{
    extern __shared__ char sm[];
    const int TW = 1 << TWsh;
    const int strideA = K * 2 + 16;
    const int Wp2 = TW + 2;
    const int rowsA = rpt * Wp2;
    const int hsh = (K == 32) ? 2 : 3;       // uint4 per row per array = K/8
    const int hc4m = (K >> 3) - 1;
    const int Bw4 = 4 * strideA;             // uint4 per tap per array
    const int tid = threadIdx.x;
    const int ocb = blockIdx.y, n = blockIdx.z;
    const int xt = blockIdx.x % xstrips, yt = blockIdx.x / xstrips;
    const int y0 = yt * rpt, x0 = xt << TWsh;

    float* ss = (float*)(sm + (size_t)rowsA * strideA * 2 + (size_t)3 * 64 * strideA * 2);
    float* bs = ss + 64;
    float* stage = (float*)sm;               // reused after final sync

    if (tid < 64) { ss[tid] = g[ocb * 64 + tid] * BN_INV; bs[tid] = b[ocb * 64 + tid]; }

    const uint32_t AhU = smem_to_u32(sm);
    const uint32_t BhU = AhU + 2 * rowsA * strideA;

    const int lane = tid & 31, warp = tid >> 5;
    const int wm = warp & 3, wn = warp >> 2;
    const int mbase = wm * 32, nbase = wn * 32;

    const int arow = lane & 15, acol = (lane >> 4) * 16;
    const int brow = (lane & 7) + ((lane >> 4) << 3), bcol = ((lane >> 3) & 1) * 16;

    int aRowBase[2];
#pragma unroll
    for (int mt = 0; mt < 2; mt++) {
        int m = mbase + mt * 16 + arow;
        aRowBase[mt] = (m >> TWsh) * Wp2 + (m & (TW - 1));
    }

    float acc[2][4][4];
#pragma unroll
    for (int i = 0; i < 2; i++)
#pragma unroll
        for (int j = 0; j < 4; j++)
#pragma unroll
            for (int k = 0; k < 4; k++) acc[i][j][k] = 0.f;

    const int totA = rowsA << hsh;

    for (int ky = 0; ky < 3; ky++) {
        for (int kc = 0; kc < nkc; kc++) {
            __syncthreads();
            // ---- A gather via cp.async (zero-fill halo) ----
            for (int i = tid; i < totA; i += 256) {
                int row = i >> hsh, j = i & hc4m;
                int seg = row / Wp2;
                int px = x0 + (row - seg * Wp2) - 1;
                int py = y0 + seg + ky - 1;
                bool ok = ((unsigned)px < (unsigned)W) && ((unsigned)py < (unsigned)H);
                long src = (((long)n * H + py) * W + px) * CW4 + kc * (CW4 >> 1) + j;
                uint32_t dA = AhU + (uint32_t)(row * strideA + j * 16);
                int sz = ok ? 16 : 0;
                asm volatile("cp.async.cg.shared.global [%0], [%1], 16, %2;"
                             :: "r"(dA), "l"(inh + src), "r"(sz) : "memory");
                asm volatile("cp.async.cg.shared.global [%0], [%1], 16, %2;"
                             :: "r"(dA + (uint32_t)(rowsA * strideA)), "l"(inl + src), "r"(sz) : "memory");
            }
            // ---- B: 3 kx taps ----
            {
                const int blk0 = (ocb * 9 + ky * 3) * nkc + kc;
                for (int i = tid; i < 3 * Bw4; i += 256) {
                    int tap = i / Bw4, r = i - tap * Bw4;
                    long gsrc = (long)(blk0 + tap * nkc) * Bw4 + r;
                    uint32_t dB = BhU + (uint32_t)i * 16;
                    asm volatile("cp.async.cg.shared.global [%0], [%1], 16;"
                                 :: "r"(dB), "l"(Bh + gsrc) : "memory");
                    asm volatile("cp.async.cg.shared.global [%0], [%1], 16;"
                                 :: "r"(dB + (uint32_t)(3 * 64 * strideA)), "l"(Bl + gsrc) : "memory");
                }
            }
            asm volatile("cp.async.commit_group;" ::: "memory");
            asm volatile("cp.async.wait_group 0;" ::: "memory");
            __syncthreads();
            // ---- MMA: 3 kx taps x K/16 ----
            for (int kx = 0; kx < 3; kx++) {
                for (int k16 = 0; k16 < (K >> 4); k16++) {
                    uint32_t ah[2][4], al[2][4], bh[2][4], bl[2][4];
#pragma unroll
                    for (int mt = 0; mt < 2; mt++) {
                        uint32_t aaddr = AhU + (uint32_t)(aRowBase[mt] + kx) * strideA
                                       + k16 * 32 + acol;
                        LDSM4(ah[mt], aaddr);
                        LDSM4(al[mt], aaddr + (uint32_t)(rowsA * strideA));
                    }
#pragma unroll
                    for (int g2 = 0; g2 < 2; g2++) {
                        uint32_t baddr = BhU + (uint32_t)(kx * 64 + nbase + g2 * 16 + brow) * strideA
                                       + k16 * 32 + bcol;
                        LDSM4(bh[g2], baddr);
                        LDSM4(bl[g2], baddr + (uint32_t)(3 * 64 * strideA));
                    }
#pragma unroll
                    for (int mt = 0; mt < 2; mt++)
#pragma unroll
                        for (int nt = 0; nt < 4; nt++) {
                            const int g2 = nt >> 1, pr = (nt & 1) * 2;
                            mma16816(acc[mt][nt], ah[mt], bh[g2][pr], bh[g2][pr + 1]);
                            mma16816(acc[mt][nt], ah[mt], bl[g2][pr], bl[g2][pr + 1]);
                            mma16816(acc[mt][nt], al[mt], bh[g2][pr], bh[g2][pr + 1]);
                        }
                }
            }
        }
    }

    // ---- epilogue: stage ([oc][pixel], stride 132) ----
    __syncthreads();
    {
        const int r0 = lane >> 2, cpair = (lane & 3) * 2;
#pragma unroll
        for (int mt = 0; mt < 2; mt++) {
            const int m1 = mbase + mt * 16 + r0, m2 = m1 + 8;
#pragma unroll
            for (int nt = 0; nt < 4; nt++) {
                const int nc = nbase + nt * 8 + cpair;
                stage[nc * 132 + m1]       = acc[mt][nt][0];
                stage[(nc + 1) * 132 + m1] = acc[mt][nt][1];
                stage[nc * 132 + m2]       = acc[mt][nt][2];
                stage[(nc + 1) * 132 + m2] = acc[mt][nt][3];
            }
        }
    }
    __syncthreads();
    // coalesced NCHW stores
    {
        const long HW = (long)H * W;
        const long obase = ((long)n * Cout + ocb * 64) * HW;
        for (int i = tid; i < 8192; i += 256) {
            int oc = i >> 7, p = i & 127;
            int y = y0 + (p >> TWsh), x = x0 + (p & (TW - 1));
            float v = fmaxf(stage[oc * 132 + p] * ss[oc] + bs[oc], 0.f);
            out[obase + (long)oc * HW + (long)y * W + x] = v;
        }
    }
    // fused 2x2 pool -> NHWC bf16 hi/lo (rpt==2 tiles only)
    if (ph) {
        const int Hp = H >> 1, Wp = W >> 1;
        const int yp = y0 >> 1, xp0 = x0 >> 1;
        for (int i = tid; i < 1024; i += 256) {
            int cw = i & 31, xx = i >> 5;
            int c0 = cw * 2, c1 = c0 + 1;
            int pa = 2 * xx, pc = TW + 2 * xx;
            float m0 = fmaxf(fmaxf(stage[c0 * 132 + pa], stage[c0 * 132 + pa + 1]),
                             fmaxf(stage[c0 * 132 + pc], stage[c0 * 132 + pc + 1]));
            float m1 = fmaxf(fmaxf(stage[c1 * 132 + pa], stage[c1 * 132 + pa + 1]),
                             fmaxf(stage[c1 * 132 + pc], stage[c1 * 132 + pc + 1]));
            float v0 = fmaxf(m0 * ss[c0] + bs[c0], 0.f);
            float v1 = fmaxf(m1 * ss[c1] + bs[c1], 0.f);
            uint32_t hw, lw;
            split2(v0, v1, hw, lw);
            long o = (((long)n * Hp + yp) * Wp + xp0 + xx) * poolCW + ocb * 32 + cw;
            ph[o] = hw; pl[o] = lw;
        }
    }
}

// ---------------- build per-channel quadratic form A = Re(U^H diag(zbar) U) --
__global__ void build_A_kernel(const float* __restrict__ w0,
                               const float* __restrict__ w1,
                               float* __restrict__ A)
{
    int t = blockIdx.x * blockDim.x + threadIdx.x;
    if (t >= 256 * 16) return;
    int c = t >> 4, k = t & 15;
    float gr[4][2][2], gi[4][2][2];
    float a0 = w0[c*2+0], a1 = w0[c*2+1], z0 = w1[c*2+0], z1 = w1[c*2+1];
    const float isq2 = 0.7071067811865476f;
#pragma unroll
    for (int w = 0; w < 4; w++) {
        float ay = (w & 1) ? a1 : a0, az = (w & 1) ? z1 : z0;
        float cy = cosf(ay*0.5f), sy = sinf(ay*0.5f);
        float cz = cosf(az*0.5f), sz = sinf(az*0.5f);
        float m00 = (cy-sy)*isq2, m01 = (cy+sy)*isq2;
        float m10 = (sy+cy)*isq2, m11 = (sy-cy)*isq2;
        gr[w][0][0]=m00*cz; gi[w][0][0]=-m00*sz;
        gr[w][0][1]=m01*cz; gi[w][0][1]=-m01*sz;
        gr[w][1][0]=m10*cz; gi[w][1][0]= m10*sz;
        gr[w][1][1]=m11*cz; gi[w][1][1]= m11*sz;
    }
    int P[16];
#pragma unroll
    for (int bb = 0; bb < 16; bb++) {
        int v = bb;
        if (v & 1) v ^= 8;
        if (v & 2) v ^= 1;
        if (v & 4) v ^= 2;
        if (v & 8) v ^= 4;
        P[bb] = v;
    }
    float acc[16];
#pragma unroll
    for (int j = 0; j < 16; j++) acc[j] = 0.f;
    for (int i = 0; i < 16; i++) {
        int r = P[i];
        float zi = (4 - 2 * __popc(i)) * 0.25f;
        int r0=(r>>3)&1, r1=(r>>2)&1, r2=(r>>1)&1, r3=r&1;
        float t2r[2], t2i[2];
        t2r[0]=gr[0][r0][0]; t2i[0]=gi[0][r0][0];
        t2r[1]=gr[0][r0][1]; t2i[1]=gi[0][r0][1];
        float t4r[4], t4i[4];
#pragma unroll
        for (int j0 = 0; j0 < 2; j0++)
#pragma unroll
            for (int j1 = 0; j1 < 2; j1++) {
                float br=gr[1][r1][j1], bi=gi[1][r1][j1];
                t4r[j0*2+j1]=t2r[j0]*br-t2i[j0]*bi;
                t4i[j0*2+j1]=t2r[j0]*bi+t2i[j0]*br;
            }
        float t8r[8], t8i[8];
#pragma unroll
        for (int j = 0; j < 4; j++)
#pragma unroll
            for (int j2 = 0; j2 < 2; j2++) {
                float br=gr[2][r2][j2], bi=gi[2][r2][j2];
                t8r[j*2+j2]=t4r[j]*br-t4i[j]*bi;
                t8i[j*2+j2]=t4r[j]*bi+t4i[j]*br;
            }
        float ur[16], ui[16];
#pragma unroll
        for (int j = 0; j < 8; j++)
#pragma unroll
            for (int j3 = 0; j3 < 2; j3++) {
                float br=gr[3][r3][j3], bi=gi[3][r3][j3];
                ur[j*2+j3]=t8r[j]*br-t8i[j]*bi;
                ui[j*2+j3]=t8r[j]*bi+t8i[j]*br;
            }
        float ukr = ur[k], uki = ui[k];
#pragma unroll
        for (int j = 0; j < 16; j++)
            acc[j] += zi * (ur[j]*ukr + ui[j]*uki);
    }
#pragma unroll
    for (int j = 0; j < 16; j++) A[c*256 + j*16 + k] = acc[j];
}

// ---------------- quantum stage + BN5 + ReLU (fused) -------------------------
__global__ __launch_bounds__(256) void quantum_kernel(
    const float* __restrict__ e4, const float* __restrict__ A,
    const float* __restrict__ g5, const float* __restrict__ b5,
    float* __restrict__ out)
{
    __shared__ float tile[35 * 37];
    __shared__ float As[256];
    const int bc = blockIdx.x, c = bc & 255, tid = threadIdx.x;
    for (int i = tid; i < 35 * 37; i += 256) tile[i] = 0.f;
    __syncthreads();
    const float* ep = e4 + (long)bc * 1024;
    for (int i = tid; i < 1024; i += 256) {
        int r = i >> 5, cc = i & 31;
        tile[(r + 1) * 37 + (cc + 1)] = ep[i];
    }
    if (tid < 256) As[tid] = A[c * 256 + tid];
    __syncthreads();
    const int y = tid >> 3, x4 = (tid & 7) * 4;
    float win[4][7];
#pragma unroll
    for (int r = 0; r < 4; r++)
#pragma unroll
        for (int cc = 0; cc < 7; cc++) win[r][cc] = tile[(y + r) * 37 + x4 + cc];
    float s[4] = {0.f, 0.f, 0.f, 0.f};
#pragma unroll
    for (int o = 0; o < 4; o++)
#pragma unroll
        for (int t = 0; t < 16; t++) {
            float v = win[t >> 2][(t & 3) + o];
            s[o] += v * v;
        }
    float quad[4] = {0.f, 0.f, 0.f, 0.f};
#pragma unroll
    for (int j = 0; j < 16; j++) {
        float t0 = 0.f, t1 = 0.f, t2 = 0.f, t3 = 0.f;
        int jr = j >> 2, jc = j & 3;
#pragma unroll
        for (int k = 0; k < 16; k++) {
            float a = As[j * 16 + k];
            int kr = k >> 2, kc = k & 3;
            t0 += a * win[kr][kc + 0];
            t1 += a * win[kr][kc + 1];
            t2 += a * win[kr][kc + 2];
            t3 += a * win[kr][kc + 3];
        }
        quad[0] += t0 * win[jr][jc + 0];
        quad[1] += t1 * win[jr][jc + 1];
        quad[2] += t2 * win[jr][jc + 2];
        quad[3] += t3 * win[jr][jc + 3];
    }
    const float sc = g5[c] * BN_INV, bb = b5[c];
    float4 v;
    v.x = fmaxf((0.5f*quad[0]/fmaxf(s[0],1e-24f)+0.5f)*sc+bb, 0.f);
    v.y = fmaxf((0.5f*quad[1]/fmaxf(s[1],1e-24f)+0.5f)*sc+bb, 0.f);
    v.z = fmaxf((0.5f*quad[2]/fmaxf(s[2],1e-24f)+0.5f)*sc+bb, 0.f);
    v.w = fmaxf((0.5f*quad[3]/fmaxf(s[3],1e-24f)+0.5f)*sc+bb, 0.f);
    *(float4*)(out + (long)bc * 1024 + y * 32 + x4) = v;
}

// -----------------------------------------------------------------------------
// dyn smem: conv2 52352, conv3 93824, conv4 94976
extern "C" void kernel_launch(void* const* d_in, const int* in_sizes, int n_in,
                              void* d_out, int out_size)
{
    (void)in_sizes; (void)n_in; (void)out_size;
    const float* x   = (const float*)d_in[0];
    const float* w1  = (const float*)d_in[1];
    const float* g1  = (const float*)d_in[2];
    const float* b1  = (const float*)d_in[3];
    const float* w2  = (const float*)d_in[4];
    const float* g2  = (const float*)d_in[5];
    const float* b2  = (const float*)d_in[6];
    const float* w3  = (const float*)d_in[7];
    const float* g3  = (const float*)d_in[8];
    const float* b3  = (const float*)d_in[9];
    const float* w4  = (const float*)d_in[10];
    const float* g4  = (const float*)d_in[11];
    const float* b4  = (const float*)d_in[12];
    const float* qw0 = (const float*)d_in[13];
    const float* qw1 = (const float*)d_in[14];
    const float* g5  = (const float*)d_in[15];
    const float* b5  = (const float*)d_in[16];

    float* out = (float*)d_out;
    float* e1 = out;
    float* e2 = out + 16777216;
    float* e3 = out + 25165824;
    float* o4 = out + 29360128;

    uint32_t *p1h, *p1l, *p2h, *p2l, *p3h, *p3l;
    uint16_t *B2h, *B2l, *B3h, *B3l, *B4h, *B4l;
    float *e4, *Ab;
    cudaGetSymbolAddress((void**)&p1h, g_p1h); cudaGetSymbolAddress((void**)&p1l, g_p1l);
    cudaGetSymbolAddress((void**)&p2h, g_p2h); cudaGetSymbolAddress((void**)&p2l, g_p2l);
    cudaGetSymbolAddress((void**)&p3h, g_p3h); cudaGetSymbolAddress((void**)&p3l, g_p3l);
    cudaGetSymbolAddress((void**)&B2h, g_B2h); cudaGetSymbolAddress((void**)&B2l, g_B2l);
    cudaGetSymbolAddress((void**)&B3h, g_B3h); cudaGetSymbolAddress((void**)&B3l, g_B3l);
    cudaGetSymbolAddress((void**)&B4h, g_B4h); cudaGetSymbolAddress((void**)&B4l, g_B4l);
    cudaGetSymbolAddress((void**)&e4, g_e4);   cudaGetSymbolAddress((void**)&Ab, g_A);

    cudaFuncSetAttribute(conv_mma_kernel, cudaFuncAttributeMaxDynamicSharedMemorySize, 94976);

    // conv1 + pool1 fused -> e1, p1
    conv1_pool_kernel<<<dim3(4, 16, 8), 256>>>(x, w1, g1, b1, e1, p1h, p1l);
    // weight packing (single launch)
    pack_all_kernel<<<1512, 256>>>(w2, w3, w4, B2h, B2l, B3h, B3l, B4h, B4l);
    // conv2 -> e2 (8,64,128,128), fused pool2 -> p2 (NHWC 64ch @64x64)
    conv_mma_kernel<<<dim3(128, 1, 8), 256, 52352>>>(
        (const uint4*)p1h, (const uint4*)p1l, (const uint4*)B2h, (const uint4*)B2l,
        g2, b2, e2, 128, 128, 6, 2, 32, 4, 1, 64, 2, p2h, p2l, 32);
    // conv3 -> e3 (8,128,64,64), fused pool3 -> p3 (NHWC 128ch @32x32)
    conv_mma_kernel<<<dim3(32, 2, 8), 256, 93824>>>(
        (const uint4*)p2h, (const uint4*)p2l, (const uint4*)B3h, (const uint4*)B3l,
        g3, b3, e3, 64, 64, 6, 2, 64, 8, 1, 128, 1, p3h, p3l, 64);
    // conv4 -> e4 (8,256,32,32), no pool
    conv_mma_kernel<<<dim3(8, 4, 8), 256, 94976>>>(
        (const uint4*)p3h, (const uint4*)p3l, (const uint4*)B4h, (const uint4*)B4l,
        g4, b4, e4, 32, 32, 5, 4, 64, 16, 2, 256, 1, (uint32_t*)0, (uint32_t*)0, 0);
    // quantum
    build_A_kernel<<<16, 256>>>(qw0, qw1, Ab);
    quantum_kernel<<<2048, 256>>>(e4, Ab, g5, b5, o4);
}